// round 10
// baseline (speedup 1.0000x reference)
#include <cuda_runtime.h>
#include <cuda_bf16.h>
#include <math.h>
#include <stdint.h>

#define T 2048
#define H 4096
#define NH 32
#define NKV 8
#define HD 128
#define QKVW ((NH + 2 * NKV) * HD)   /* 6144 */
#define SCALE 0.08838834764831845f   /* HD^-0.5 */

// ---------------- scratch (static device memory; no allocs allowed) ----------
__device__ float g_qkv[T * QKVW];                                  // fp32 QKV
__device__ __align__(256) __nv_bfloat16 g_ah[T * H],      g_al[T * H];        // A planes
__device__ __align__(256) __nv_bfloat16 g_bh[H * QKVW],   g_bl[H * QKVW];     // B planes ([N][K])
__device__ __align__(256) __nv_bfloat16 g_qh[T * NH * HD], g_ql[T * NH * HD];
__device__ __align__(256) __nv_bfloat16 g_kh[T * NKV * HD], g_kl[T * NKV * HD];
__device__ __align__(256) __nv_bfloat16 g_vth[NKV * HD * T], g_vtl[NKV * HD * T]; // V^T [hkv][d][t]

// ================= helpers ================
__device__ __forceinline__ void mma_bf16(float c[4],
    uint32_t a0, uint32_t a1, uint32_t a2, uint32_t a3,
    uint32_t b0, uint32_t b1)
{
    asm volatile(
        "mma.sync.aligned.m16n8k16.row.col.f32.bf16.bf16.f32 "
        "{%0,%1,%2,%3},{%4,%5,%6,%7},{%8,%9},{%0,%1,%2,%3};\n"
        : "+f"(c[0]), "+f"(c[1]), "+f"(c[2]), "+f"(c[3])
        : "r"(a0), "r"(a1), "r"(a2), "r"(a3), "r"(b0), "r"(b1));
}

#define LDSM4(r0, r1, r2, r3, addr) \
    asm volatile("ldmatrix.sync.aligned.m8n8.x4.shared.b16 {%0,%1,%2,%3}, [%4];" \
        : "=r"(r0), "=r"(r1), "=r"(r2), "=r"(r3) : "r"(addr))

__device__ __forceinline__ uint32_t pack_hi16(float x0, float x1)
{
    uint32_t r;
    asm("prmt.b32 %0, %1, %2, 0x7632;"
        : "=r"(r) : "r"(__float_as_uint(x0)), "r"(__float_as_uint(x1)));
    return r;
}

__device__ __forceinline__ void split2(float x0, float x1, uint32_t& h, uint32_t& l)
{
    h = pack_hi16(x0, x1);
    float l0 = x0 - __uint_as_float(__float_as_uint(x0) & 0xffff0000u);
    float l1 = x1 - __uint_as_float(__float_as_uint(x1) & 0xffff0000u);
    l = pack_hi16(l0, l1);
}

__device__ __forceinline__ void split1(float v, uint16_t& h16, uint16_t& l16)
{
    uint32_t u = __float_as_uint(v);
    h16 = (uint16_t)(u >> 16);
    float lo = v - __uint_as_float(u & 0xffff0000u);
    l16 = (uint16_t)(__float_as_uint(lo) >> 16);
}

__device__ __forceinline__ void cp_async16(uint32_t dst, const void* src)
{
    asm volatile("cp.async.cg.shared.global [%0], [%1], 16;\n"
                 :: "r"(dst), "l"(src));
}

// ================= prep kernels ================
__global__ void split_plane(const float2* __restrict__ in,
    uint32_t* __restrict__ hi, uint32_t* __restrict__ lo, int npairs)
{
    for (int i = blockIdx.x * blockDim.x + threadIdx.x; i < npairs;
         i += gridDim.x * blockDim.x) {
        float2 v = in[i];
        uint32_t h, l;
        split2(v.x, v.y, h, l);
        hi[i] = h; lo[i] = l;
    }
}

__global__ void split_transpose(const float* __restrict__ B,
    __nv_bfloat16* __restrict__ Bth, __nv_bfloat16* __restrict__ Btl,
    int K, int N)
{
    __shared__ float tile[32][33];
    int n0 = blockIdx.x * 32, k0 = blockIdx.y * 32;
    int tx = threadIdx.x, ty = threadIdx.y;
#pragma unroll
    for (int i = 0; i < 4; i++)
        tile[ty + 8 * i][tx] = B[(size_t)(k0 + ty + 8 * i) * N + n0 + tx];
    __syncthreads();
#pragma unroll
    for (int i = 0; i < 4; i++) {
        float v = tile[tx][ty + 8 * i];
        uint16_t h16, l16;
        split1(v, h16, l16);
        size_t o = (size_t)(n0 + ty + 8 * i) * K + k0 + tx;
        ((uint16_t*)Bth)[o] = h16;
        ((uint16_t*)Btl)[o] = l16;
    }
}

__global__ void split_transpose_v()
{
    __shared__ float tile[32][33];
    int t0 = blockIdx.x * 32, d0 = blockIdx.y * 32, hkv = blockIdx.z;
    int tx = threadIdx.x, ty = threadIdx.y;
#pragma unroll
    for (int i = 0; i < 4; i++)
        tile[ty + 8 * i][tx] =
            g_qkv[(size_t)(t0 + ty + 8 * i) * QKVW + (NH + NKV) * HD + hkv * HD + d0 + tx];
    __syncthreads();
#pragma unroll
    for (int i = 0; i < 4; i++) {
        float v = tile[tx][ty + 8 * i];
        uint16_t h16, l16;
        split1(v, h16, l16);
        size_t o = (size_t)hkv * HD * T + (size_t)(d0 + ty + 8 * i) * T + t0 + tx;
        ((uint16_t*)g_vth)[o] = h16;
        ((uint16_t*)g_vtl)[o] = l16;
    }
}

// ================= plane GEMM: ldmatrix + HMMA mainloop ================
// C[M,N] = A[M,K] @ B[K,N]; A planes [M][K], Bt planes [N][K], all bf16.
// BM=BN=128, BK=32, 256 threads, warp tile 64x32, cp.async 2-stage.
#define PSTRIDE 20                    /* uint32 pairs per row (80 B pitch, 5x16B -> cf) */
#define TILE_U32 (128 * PSTRIDE)      /* 2560 */
#define TILE_B   (TILE_U32 * 4)       /* 10240 bytes */
#define STAGE_U32 (4 * TILE_U32)      /* AsH AsL BsH BsL */
#define GEMM_SMEM (2 * STAGE_U32 * 4) /* 81920 B */

__global__ __launch_bounds__(256, 2) void gemm_planes(
    const __nv_bfloat16* __restrict__ Ah, const __nv_bfloat16* __restrict__ Al,
    const __nv_bfloat16* __restrict__ Bh, const __nv_bfloat16* __restrict__ Bl,
    float* __restrict__ C, int M, int N, int K)
{
    extern __shared__ uint32_t smu[];
    int tid  = threadIdx.x;
    int warp = tid >> 5, lane = tid & 31;
    int gid  = lane >> 2, t4 = lane & 3;
    int wm   = (warp >> 2) * 64;
    int wn   = (warp & 3) * 32;
    int bm   = blockIdx.y * 128;
    int bn   = blockIdx.x * 128;

    float acc[4][4][4];
#pragma unroll
    for (int mi = 0; mi < 4; mi++)
#pragma unroll
        for (int ni = 0; ni < 4; ni++)
#pragma unroll
            for (int r = 0; r < 4; r++) acc[mi][ni][r] = 0.f;

    uint32_t smbase = (uint32_t)__cvta_generic_to_shared(smu);
    // per-lane ldmatrix offset: row (lane&15), k-chunk (lane>>4)*16B
    uint32_t lmoff = (uint32_t)((lane & 15) * 80 + (lane >> 4) * 16);

    int lr = tid >> 2;     // 0..63
    int lc = tid & 3;      // 16B chunk within 64B row

    auto load_stage = [&](int s, int kt) {
        uint32_t base = smbase + s * STAGE_U32 * 4;
#pragma unroll
        for (int half = 0; half < 2; half++) {
            int r = lr + 64 * half;
            uint32_t d = base + (r * PSTRIDE + lc * 4) * 4;
            cp_async16(d,              Ah + (size_t)(bm + r) * K + kt + lc * 8);
            cp_async16(d + TILE_B,     Al + (size_t)(bm + r) * K + kt + lc * 8);
            cp_async16(d + 2 * TILE_B, Bh + (size_t)(bn + r) * K + kt + lc * 8);
            cp_async16(d + 3 * TILE_B, Bl + (size_t)(bn + r) * K + kt + lc * 8);
        }
        asm volatile("cp.async.commit_group;\n");
    };

    load_stage(0, 0);
    int niter = K >> 5;

    for (int it = 0; it < niter; it++) {
        int s = it & 1;
        if (it + 1 < niter) {
            load_stage(s ^ 1, (it + 1) << 5);
            asm volatile("cp.async.wait_group 1;\n");
        } else {
            asm volatile("cp.async.wait_group 0;\n");
        }
        __syncthreads();

        uint32_t aH = smbase + s * STAGE_U32 * 4;
        uint32_t bH = aH + 2 * TILE_B;

#pragma unroll
        for (int kp0 = 0; kp0 < 16; kp0 += 8) {
            uint32_t kb = kp0 * 4;
            uint32_t ahf[4][4], alf[4][4];
#pragma unroll
            for (int mi = 0; mi < 4; mi++) {
                uint32_t ra = aH + (uint32_t)((wm + mi * 16) * 80) + kb + lmoff;
                LDSM4(ahf[mi][0], ahf[mi][1], ahf[mi][2], ahf[mi][3], ra);
                LDSM4(alf[mi][0], alf[mi][1], alf[mi][2], alf[mi][3], ra + TILE_B);
            }
#pragma unroll
            for (int nt = 0; nt < 2; nt++) {
                uint32_t rb = bH + (uint32_t)((wn + nt * 16) * 80) + kb + lmoff;
                uint32_t h0, h1, h2, h3, l0, l1, l2, l3;
                LDSM4(h0, h1, h2, h3, rb);
                LDSM4(l0, l1, l2, l3, rb + TILE_B);
#pragma unroll
                for (int mi = 0; mi < 4; mi++) {
                    // n-tile 2*nt: b-frag (h0,h2); n-tile 2*nt+1: (h1,h3)
                    mma_bf16(acc[mi][2 * nt], ahf[mi][0], ahf[mi][1], ahf[mi][2], ahf[mi][3], h0, h2);
                    mma_bf16(acc[mi][2 * nt], ahf[mi][0], ahf[mi][1], ahf[mi][2], ahf[mi][3], l0, l2);
                    mma_bf16(acc[mi][2 * nt], alf[mi][0], alf[mi][1], alf[mi][2], alf[mi][3], h0, h2);
                    mma_bf16(acc[mi][2 * nt + 1], ahf[mi][0], ahf[mi][1], ahf[mi][2], ahf[mi][3], h1, h3);
                    mma_bf16(acc[mi][2 * nt + 1], ahf[mi][0], ahf[mi][1], ahf[mi][2], ahf[mi][3], l1, l3);
                    mma_bf16(acc[mi][2 * nt + 1], alf[mi][0], alf[mi][1], alf[mi][2], alf[mi][3], h1, h3);
                }
            }
        }
        __syncthreads();
    }

#pragma unroll
    for (int mi = 0; mi < 4; mi++)
#pragma unroll
        for (int ni = 0; ni < 4; ni++) {
            int row = bm + wm + mi * 16 + gid;
            int col = bn + wn + ni * 8 + t4 * 2;
            *(float2*)&C[(size_t)row * N + col] =
                make_float2(acc[mi][ni][0], acc[mi][ni][1]);
            *(float2*)&C[(size_t)(row + 8) * N + col] =
                make_float2(acc[mi][ni][2], acc[mi][ni][3]);
        }
}

// ---------------- LayerNorm + interleaved RoPE -> Q/K bf16 planes ------------
__global__ __launch_bounds__(128) void norm_rope_kernel(
    const int* __restrict__ positions,
    const float* __restrict__ qw, const float* __restrict__ kw)
{
    int t  = blockIdx.x;
    int hh = blockIdx.y;
    bool is_q = hh < NH;
    int head  = is_q ? hh : hh - NH;
    int base  = t * QKVW + (is_q ? head * HD : NH * HD + head * HD);
    int c = threadIdx.x;

    float x = g_qkv[base + c];

    __shared__ float red[4];
    __shared__ float ybuf[HD];

    float s = x;
#pragma unroll
    for (int o = 16; o; o >>= 1) s += __shfl_xor_sync(0xffffffffu, s, o);
    if ((c & 31) == 0) red[c >> 5] = s;
    __syncthreads();
    float mean = (red[0] + red[1] + red[2] + red[3]) * (1.0f / HD);
    __syncthreads();

    float d  = x - mean;
    float s2 = d * d;
#pragma unroll
    for (int o = 16; o; o >>= 1) s2 += __shfl_xor_sync(0xffffffffu, s2, o);
    if ((c & 31) == 0) red[c >> 5] = s2;
    __syncthreads();
    float var = (red[0] + red[1] + red[2] + red[3]) * (1.0f / HD);

    float w = is_q ? qw[head * HD + c] : kw[head * HD + c];
    ybuf[c] = d * rsqrtf(var + 1e-5f) * w;
    __syncthreads();

    if (c < HD / 2) {
        float x1 = ybuf[2 * c], x2 = ybuf[2 * c + 1];
        float fpos = (float)positions[t];
        float inv_freq = exp2f(-((float)(2 * c) * (1.0f / HD)) * 13.287712379549449f);
        float f = fpos * inv_freq;
        float sn, cs;
        sincosf(f, &sn, &cs);
        float o1 = x1 * cs - x2 * sn;
        float o2 = x2 * cs + x1 * sn;
        uint32_t hh32, ll32;
        if (is_q) {
            split2(o1 * SCALE, o2 * SCALE, hh32, ll32);
            ((uint32_t*)g_qh)[(size_t)t * 2048 + head * 64 + c] = hh32;
            ((uint32_t*)g_ql)[(size_t)t * 2048 + head * 64 + c] = ll32;
        } else {
            split2(o1, o2, hh32, ll32);
            ((uint32_t*)g_kh)[(size_t)t * 512 + head * 64 + c] = hh32;
            ((uint32_t*)g_kl)[(size_t)t * 512 + head * 64 + c] = ll32;
        }
    }
}

// ================= flash attention: ldmatrix + HMMA mainloop ==============
// BM=128, BN=64, 256 thr = 8 warps; warp owns 16 Q rows; state in registers.
// Pitches: Q/K 68 pairs = 272 B (17x16B, cf); V^T/P 36 pairs = 144 B (9x16B, cf).
#define QP 68
#define VP 36
#define FLASH_SMEM ((2 * 128 * QP + 2 * 64 * QP + 2 * 128 * VP + 2 * 128 * VP) * 4)

__global__ __launch_bounds__(256) void flash_mma_kernel()
{
    extern __shared__ uint32_t smu[];
    uint32_t* QH = smu;
    uint32_t* QL = QH + 128 * QP;
    uint32_t* KH = QL + 128 * QP;
    uint32_t* KL = KH + 64 * QP;
    uint32_t* VH = KL + 64 * QP;
    uint32_t* VL = VH + 128 * VP;
    uint32_t* PH = VL + 128 * VP;
    uint32_t* PL = PH + 128 * VP;

    int qb  = (gridDim.x - 1) - blockIdx.x;
    int h   = blockIdx.y;
    int hkv = h >> 2;
    int tid = threadIdx.x;
    int w   = tid >> 5, lane = tid & 31;
    int gid = lane >> 2, t4 = lane & 3;
    int r0  = w * 16;

    // byte-address bases for ldmatrix
    uint32_t fbase = (uint32_t)__cvta_generic_to_shared(smu);
    uint32_t FQH = fbase;
    uint32_t FQL = FQH + 128 * QP * 4;
    uint32_t FKH = FQL + 128 * QP * 4;
    uint32_t FKL = FKH + 64 * QP * 4;
    uint32_t FVH = FKL + 64 * QP * 4;
    uint32_t FVL = FVH + 128 * VP * 4;
    uint32_t FPH = FVL + 128 * VP * 4;
    uint32_t FPL = FPH + 128 * VP * 4;
    uint32_t lm272 = (uint32_t)((lane & 15) * 272 + (lane >> 4) * 16);
    uint32_t lm144 = (uint32_t)((lane & 15) * 144 + (lane >> 4) * 16);

    {
        const uint4* qh4 = (const uint4*)g_qh + ((size_t)(qb * 128) * (NH * HD) + h * HD) / 8;
        const uint4* ql4 = (const uint4*)g_ql + ((size_t)(qb * 128) * (NH * HD) + h * HD) / 8;
        for (int idx = tid; idx < 128 * 16; idx += 256) {
            int r = idx >> 4, u = idx & 15;
            *(uint4*)&QH[r * QP + u * 4] = qh4[r * 512 + u];
            *(uint4*)&QL[r * QP + u * 4] = ql4[r * 512 + u];
        }
    }

    float of[16][4];
#pragma unroll
    for (int ni = 0; ni < 16; ni++)
#pragma unroll
        for (int r = 0; r < 4; r++) of[ni][r] = 0.f;
    float mst0 = -1e30f, mst1 = -1e30f, lst0 = 0.f, lst1 = 0.f;

    int nkb = 2 * qb + 2;
    for (int kb = 0; kb < nkb; kb++) {
        __syncthreads();

        {
            const uint4* kh4 = (const uint4*)g_kh + ((size_t)(kb * 64) * (NKV * HD) + hkv * HD) / 8;
            const uint4* kl4 = (const uint4*)g_kl + ((size_t)(kb * 64) * (NKV * HD) + hkv * HD) / 8;
            for (int idx = tid; idx < 64 * 16; idx += 256) {
                int r = idx >> 4, u = idx & 15;
                *(uint4*)&KH[r * QP + u * 4] = kh4[r * 128 + u];
                *(uint4*)&KL[r * QP + u * 4] = kl4[r * 128 + u];
            }
        }
        {
            const uint4* vh4 = (const uint4*)g_vth + ((size_t)hkv * HD * T + (size_t)kb * 64) / 8;
            const uint4* vl4 = (const uint4*)g_vtl + ((size_t)hkv * HD * T + (size_t)kb * 64) / 8;
            for (int idx = tid; idx < 128 * 8; idx += 256) {
                int d = idx >> 3, u = idx & 7;
                *(uint4*)&VH[d * VP + u * 4] = vh4[d * 256 + u];
                *(uint4*)&VL[d * VP + u * 4] = vl4[d * 256 + u];
            }
        }
        __syncthreads();

        // ---- S = Q @ K^T : 8 k16 slabs, ldmatrix frags ----
        float sf[8][4];
#pragma unroll
        for (int ni = 0; ni < 8; ni++)
#pragma unroll
            for (int r = 0; r < 4; r++) sf[ni][r] = 0.f;

#pragma unroll
        for (int ks = 0; ks < 8; ks++) {
            uint32_t kbb = (uint32_t)(ks * 32);
            uint32_t aq = FQH + (uint32_t)(r0 * 272) + kbb + lm272;
            uint32_t a0, a1, a2, a3, e0, e1, e2, e3;
            LDSM4(a0, a1, a2, a3, aq);
            LDSM4(e0, e1, e2, e3, aq + (FQL - FQH));
#pragma unroll
            for (int g = 0; g < 4; g++) {
                uint32_t rk = FKH + (uint32_t)(g * 16 * 272) + kbb + lm272;
                uint32_t h0, h1, h2, h3, l0, l1, l2, l3;
                LDSM4(h0, h1, h2, h3, rk);
                LDSM4(l0, l1, l2, l3, rk + (FKL - FKH));
                mma_bf16(sf[2 * g],     a0, a1, a2, a3, h0, h2);
                mma_bf16(sf[2 * g],     a0, a1, a2, a3, l0, l2);
                mma_bf16(sf[2 * g],     e0, e1, e2, e3, h0, h2);
                mma_bf16(sf[2 * g + 1], a0, a1, a2, a3, h1, h3);
                mma_bf16(sf[2 * g + 1], a0, a1, a2, a3, l1, l3);
                mma_bf16(sf[2 * g + 1], e0, e1, e2, e3, h1, h3);
            }
        }

        if (kb >= 2 * qb) {
            int R0 = qb * 128 + r0 + gid;
            int R1 = R0 + 8;
            int jb = kb * 64;
#pragma unroll
            for (int ni = 0; ni < 8; ni++) {
                int c0 = jb + ni * 8 + t4 * 2;
                if (c0     > R0) sf[ni][0] = -1e30f;
                if (c0 + 1 > R0) sf[ni][1] = -1e30f;
                if (c0     > R1) sf[ni][2] = -1e30f;
                if (c0 + 1 > R1) sf[ni][3] = -1e30f;
            }
        }

        float mx0 = -1e30f, mx1 = -1e30f;
#pragma unroll
        for (int ni = 0; ni < 8; ni++) {
            mx0 = fmaxf(mx0, fmaxf(sf[ni][0], sf[ni][1]));
            mx1 = fmaxf(mx1, fmaxf(sf[ni][2], sf[ni][3]));
        }
        mx0 = fmaxf(mx0, __shfl_xor_sync(0xffffffffu, mx0, 1));
        mx0 = fmaxf(mx0, __shfl_xor_sync(0xffffffffu, mx0, 2));
        mx1 = fmaxf(mx1, __shfl_xor_sync(0xffffffffu, mx1, 1));
        mx1 = fmaxf(mx1, __shfl_xor_sync(0xffffffffu, mx1, 2));

        float mn0 = fmaxf(mst0, mx0), mn1 = fmaxf(mst1, mx1);
        float a0s = __expf(mst0 - mn0), a1s = __expf(mst1 - mn1);
        mst0 = mn0; mst1 = mn1;

        float ls0 = 0.f, ls1 = 0.f;
#pragma unroll
        for (int ni = 0; ni < 8; ni++) {
            sf[ni][0] = __expf(sf[ni][0] - mn0);
            sf[ni][1] = __expf(sf[ni][1] - mn0);
            sf[ni][2] = __expf(sf[ni][2] - mn1);
            sf[ni][3] = __expf(sf[ni][3] - mn1);
            ls0 += sf[ni][0] + sf[ni][1];
            ls1 += sf[ni][2] + sf[ni][3];
        }
        ls0 += __shfl_xor_sync(0xffffffffu, ls0, 1);
        ls0 += __shfl_xor_sync(0xffffffffu, ls0, 2);
        ls1 += __shfl_xor_sync(0xffffffffu, ls1, 1);
        ls1 += __shfl_xor_sync(0xffffffffu, ls1, 2);
        lst0 = a0s * lst0 + ls0;
        lst1 = a1s * lst1 + ls1;

#pragma unroll
        for (int ni = 0; ni < 16; ni++) {
            of[ni][0] *= a0s; of[ni][1] *= a0s;
            of[ni][2] *= a1s; of[ni][3] *= a1s;
        }

#pragma unroll
        for (int ni = 0; ni < 8; ni++) {
            uint32_t ph, pl;
            split2(sf[ni][0], sf[ni][1], ph, pl);
            PH[(r0 + gid) * VP + ni * 4 + t4] = ph;
            PL[(r0 + gid) * VP + ni * 4 + t4] = pl;
            split2(sf[ni][2], sf[ni][3], ph, pl);
            PH[(r0 + gid + 8) * VP + ni * 4 + t4] = ph;
            PL[(r0 + gid + 8) * VP + ni * 4 + t4] = pl;
        }
        __syncthreads();

        // ---- O += P @ V : 4 k16 slabs, ldmatrix frags ----
#pragma unroll
        for (int ks = 0; ks < 4; ks++) {
            uint32_t kbb = (uint32_t)(ks * 32);
            uint32_t ap = FPH + (uint32_t)(r0 * 144) + kbb + lm144;
            uint32_t a0, a1, a2, a3, e0, e1, e2, e3;
            LDSM4(a0, a1, a2, a3, ap);
            LDSM4(e0, e1, e2, e3, ap + (FPL - FPH));
#pragma unroll
            for (int g = 0; g < 8; g++) {
                uint32_t rv = FVH + (uint32_t)(g * 16 * 144) + kbb + lm144;
                uint32_t h0, h1, h2, h3, l0, l1, l2, l3;
                LDSM4(h0, h1, h2, h3, rv);
                LDSM4(l0, l1, l2, l3, rv + (FVL - FVH));
                mma_bf16(of[2 * g],     a0, a1, a2, a3, h0, h2);
                mma_bf16(of[2 * g],     a0, a1, a2, a3, l0, l2);
                mma_bf16(of[2 * g],     e0, e1, e2, e3, h0, h2);
                mma_bf16(of[2 * g + 1], a0, a1, a2, a3, h1, h3);
                mma_bf16(of[2 * g + 1], a0, a1, a2, a3, l1, l3);
                mma_bf16(of[2 * g + 1], e0, e1, e2, e3, h1, h3);
            }
        }
    }

    float li0 = 1.0f / lst0, li1 = 1.0f / lst1;
    int R0 = qb * 128 + r0 + gid;
    int R1 = R0 + 8;
    uint32_t* pah = (uint32_t*)g_ah;
    uint32_t* pal = (uint32_t*)g_al;
#pragma unroll
    for (int ni = 0; ni < 16; ni++) {
        int colp = h * 64 + ni * 4 + t4;
        uint32_t hh32, ll32;
        split2(of[ni][0] * li0, of[ni][1] * li0, hh32, ll32);
        pah[(size_t)R0 * 2048 + colp] = hh32;
        pal[(size_t)R0 * 2048 + colp] = ll32;
        split2(of[ni][2] * li1, of[ni][3] * li1, hh32, ll32);
        pah[(size_t)R1 * 2048 + colp] = hh32;
        pal[(size_t)R1 * 2048 + colp] = ll32;
    }
}

// ---------------- launch ----------------
extern "C" void kernel_launch(void* const* d_in, const int* in_sizes, int n_in,
                              void* d_out, int out_size)
{
    const int*   positions = (const int*)d_in[0];
    const float* hidden    = (const float*)d_in[1];
    const float* w_qkv     = (const float*)d_in[2];
    const float* w_o       = (const float*)d_in[3];
    const float* qw        = (const float*)d_in[4];
    const float* kw        = (const float*)d_in[5];
    float*       out       = (float*)d_out;

    float* qkvp;
    __nv_bfloat16 *ahp, *alp, *bhp, *blp;
    cudaGetSymbolAddress((void**)&qkvp, g_qkv);
    cudaGetSymbolAddress((void**)&ahp, g_ah);
    cudaGetSymbolAddress((void**)&alp, g_al);
    cudaGetSymbolAddress((void**)&bhp, g_bh);
    cudaGetSymbolAddress((void**)&blp, g_bl);

    cudaFuncSetAttribute(gemm_planes,
                         cudaFuncAttributeMaxDynamicSharedMemorySize, GEMM_SMEM);
    cudaFuncSetAttribute(flash_mma_kernel,
                         cudaFuncAttributeMaxDynamicSharedMemorySize, FLASH_SMEM);

    // 1) split hidden -> A planes; split+transpose w_qkv -> B planes
    split_plane<<<4096, 256>>>((const float2*)hidden,
                               (uint32_t*)ahp, (uint32_t*)alp, T * H / 2);
    split_transpose<<<dim3(QKVW / 32, H / 32), dim3(32, 8)>>>(w_qkv, bhp, blp, H, QKVW);

    // 2) QKV projection (ldmatrix + bf16x3 HMMA)
    gemm_planes<<<dim3(QKVW / 128, T / 128), 256, GEMM_SMEM>>>(
        ahp, alp, bhp, blp, qkvp, T, QKVW, H);

    // 3) LayerNorm + RoPE -> Q/K planes; V -> transposed planes
    norm_rope_kernel<<<dim3(T, NH + NKV), 128>>>(positions, qw, kw);
    split_transpose_v<<<dim3(T / 32, HD / 32, NKV), dim3(32, 8)>>>();

    // 4) flash attention -> writes A planes directly
    flash_mma_kernel<<<dim3(T / 128, NH), 256, FLASH_SMEM>>>();

    // 5) split+transpose w_o -> B planes; output projection
    split_transpose<<<dim3(H / 32, (NH * HD) / 32), dim3(32, 8)>>>(w_o, bhp, blp, NH * HD, H);
    gemm_planes<<<dim3(H / 128, T / 128), 256, GEMM_SMEM>>>(
        ahp, alp, bhp, blp, out, T, H, NH * HD);
}

// round 11
// speedup vs baseline: 1.1481x; 1.1481x over previous
#include <cuda_runtime.h>
#include <cuda_bf16.h>
#include <math.h>
#include <stdint.h>

#define T 2048
#define H 4096
#define NH 32
#define NKV 8
#define HD 128
#define QKVW ((NH + 2 * NKV) * HD)   /* 6144 */
#define SCALE 0.08838834764831845f   /* HD^-0.5 */

// ---------------- scratch (static device memory; no allocs allowed) ----------
__device__ float g_qkv[T * QKVW];                                  // fp32 QKV
__device__ __align__(256) __nv_bfloat16 g_ah[T * H],      g_al[T * H];        // A planes
__device__ __align__(256) __nv_bfloat16 g_bh[H * QKVW],   g_bl[H * QKVW];     // B planes ([N][K])
__device__ __align__(256) __nv_bfloat16 g_qh[T * NH * HD], g_ql[T * NH * HD];
__device__ __align__(256) __nv_bfloat16 g_kh[T * NKV * HD], g_kl[T * NKV * HD];
__device__ __align__(256) __nv_bfloat16 g_vth[NKV * HD * T], g_vtl[NKV * HD * T]; // V^T [hkv][d][t]

// ================= helpers ================
__device__ __forceinline__ void mma_bf16(float c[4],
    uint32_t a0, uint32_t a1, uint32_t a2, uint32_t a3,
    uint32_t b0, uint32_t b1)
{
    asm volatile(
        "mma.sync.aligned.m16n8k16.row.col.f32.bf16.bf16.f32 "
        "{%0,%1,%2,%3},{%4,%5,%6,%7},{%8,%9},{%0,%1,%2,%3};\n"
        : "+f"(c[0]), "+f"(c[1]), "+f"(c[2]), "+f"(c[3])
        : "r"(a0), "r"(a1), "r"(a2), "r"(a3), "r"(b0), "r"(b1));
}

__device__ __forceinline__ uint32_t pack_hi16(float x0, float x1)
{
    uint32_t r;
    asm("prmt.b32 %0, %1, %2, 0x7632;"
        : "=r"(r) : "r"(__float_as_uint(x0)), "r"(__float_as_uint(x1)));
    return r;
}

__device__ __forceinline__ void split2(float x0, float x1, uint32_t& h, uint32_t& l)
{
    h = pack_hi16(x0, x1);
    float l0 = x0 - __uint_as_float(__float_as_uint(x0) & 0xffff0000u);
    float l1 = x1 - __uint_as_float(__float_as_uint(x1) & 0xffff0000u);
    l = pack_hi16(l0, l1);
}

__device__ __forceinline__ void split1(float v, uint16_t& h16, uint16_t& l16)
{
    uint32_t u = __float_as_uint(v);
    h16 = (uint16_t)(u >> 16);
    float lo = v - __uint_as_float(u & 0xffff0000u);
    l16 = (uint16_t)(__float_as_uint(lo) >> 16);
}

__device__ __forceinline__ void cp_async16(uint32_t dst, const void* src)
{
    asm volatile("cp.async.cg.shared.global [%0], [%1], 16;\n"
                 :: "r"(dst), "l"(src));
}

// ================= prep kernels ================
__global__ void split_plane(const float2* __restrict__ in,
    uint32_t* __restrict__ hi, uint32_t* __restrict__ lo, int npairs)
{
    for (int i = blockIdx.x * blockDim.x + threadIdx.x; i < npairs;
         i += gridDim.x * blockDim.x) {
        float2 v = in[i];
        uint32_t h, l;
        split2(v.x, v.y, h, l);
        hi[i] = h; lo[i] = l;
    }
}

__global__ void split_transpose(const float* __restrict__ B,
    __nv_bfloat16* __restrict__ Bth, __nv_bfloat16* __restrict__ Btl,
    int K, int N)
{
    __shared__ float tile[32][33];
    int n0 = blockIdx.x * 32, k0 = blockIdx.y * 32;
    int tx = threadIdx.x, ty = threadIdx.y;
#pragma unroll
    for (int i = 0; i < 4; i++)
        tile[ty + 8 * i][tx] = B[(size_t)(k0 + ty + 8 * i) * N + n0 + tx];
    __syncthreads();
#pragma unroll
    for (int i = 0; i < 4; i++) {
        float v = tile[tx][ty + 8 * i];
        uint16_t h16, l16;
        split1(v, h16, l16);
        size_t o = (size_t)(n0 + ty + 8 * i) * K + k0 + tx;
        ((uint16_t*)Bth)[o] = h16;
        ((uint16_t*)Btl)[o] = l16;
    }
}

__global__ void split_transpose_v()
{
    __shared__ float tile[32][33];
    int t0 = blockIdx.x * 32, d0 = blockIdx.y * 32, hkv = blockIdx.z;
    int tx = threadIdx.x, ty = threadIdx.y;
#pragma unroll
    for (int i = 0; i < 4; i++)
        tile[ty + 8 * i][tx] =
            g_qkv[(size_t)(t0 + ty + 8 * i) * QKVW + (NH + NKV) * HD + hkv * HD + d0 + tx];
    __syncthreads();
#pragma unroll
    for (int i = 0; i < 4; i++) {
        float v = tile[tx][ty + 8 * i];
        uint16_t h16, l16;
        split1(v, h16, l16);
        size_t o = (size_t)hkv * HD * T + (size_t)(d0 + ty + 8 * i) * T + t0 + tx;
        ((uint16_t*)g_vth)[o] = h16;
        ((uint16_t*)g_vtl)[o] = l16;
    }
}

// ================= plane GEMM (R8 verbatim): pure HMMA mainloop ================
#define PSTRIDE 20                    /* uint32 pairs per row: 16 data + 4 pad */
#define TILE_U32 (128 * PSTRIDE)      /* 2560 */
#define STAGE_U32 (4 * TILE_U32)      /* AsH AsL BsH BsL */
#define GEMM_SMEM (2 * STAGE_U32 * 4) /* 81920 B */

__global__ __launch_bounds__(256, 2) void gemm_planes(
    const __nv_bfloat16* __restrict__ Ah, const __nv_bfloat16* __restrict__ Al,
    const __nv_bfloat16* __restrict__ Bh, const __nv_bfloat16* __restrict__ Bl,
    float* __restrict__ C, int M, int N, int K)
{
    extern __shared__ uint32_t smu[];
    int tid  = threadIdx.x;
    int warp = tid >> 5, lane = tid & 31;
    int gid  = lane >> 2, t4 = lane & 3;
    int wm   = (warp >> 2) * 64;
    int wn   = (warp & 3) * 32;
    int bm   = blockIdx.y * 128;
    int bn   = blockIdx.x * 128;

    float acc[4][4][4];
#pragma unroll
    for (int mi = 0; mi < 4; mi++)
#pragma unroll
        for (int ni = 0; ni < 4; ni++)
#pragma unroll
            for (int r = 0; r < 4; r++) acc[mi][ni][r] = 0.f;

    uint32_t smbase = (uint32_t)__cvta_generic_to_shared(smu);
    int lr = tid >> 2;     // 0..63
    int lc = tid & 3;      // 16B chunk within 64B row

    auto load_stage = [&](int s, int kt) {
        uint32_t base = smbase + s * STAGE_U32 * 4;
#pragma unroll
        for (int half = 0; half < 2; half++) {
            int r = lr + 64 * half;
            uint32_t d = base + (r * PSTRIDE + lc * 4) * 4;
            cp_async16(d,                    Ah + (size_t)(bm + r) * K + kt + lc * 8);
            cp_async16(d + TILE_U32 * 4,     Al + (size_t)(bm + r) * K + kt + lc * 8);
            cp_async16(d + 2 * TILE_U32 * 4, Bh + (size_t)(bn + r) * K + kt + lc * 8);
            cp_async16(d + 3 * TILE_U32 * 4, Bl + (size_t)(bn + r) * K + kt + lc * 8);
        }
        asm volatile("cp.async.commit_group;\n");
    };

    load_stage(0, 0);
    int niter = K >> 5;

    for (int it = 0; it < niter; it++) {
        int s = it & 1;
        if (it + 1 < niter) {
            load_stage(s ^ 1, (it + 1) << 5);
            asm volatile("cp.async.wait_group 1;\n");
        } else {
            asm volatile("cp.async.wait_group 0;\n");
        }
        __syncthreads();

        const uint32_t* AsH = smu + s * STAGE_U32;
        const uint32_t* AsL = AsH + TILE_U32;
        const uint32_t* BsH = AsH + 2 * TILE_U32;
        const uint32_t* BsL = AsH + 3 * TILE_U32;

#pragma unroll
        for (int kp0 = 0; kp0 < 16; kp0 += 8) {
            uint32_t bhf[4][2], blf[4][2];
#pragma unroll
            for (int ni = 0; ni < 4; ni++) {
                int n = wn + ni * 8 + gid;
                bhf[ni][0] = BsH[n * PSTRIDE + kp0 + t4];
                bhf[ni][1] = BsH[n * PSTRIDE + kp0 + 4 + t4];
                blf[ni][0] = BsL[n * PSTRIDE + kp0 + t4];
                blf[ni][1] = BsL[n * PSTRIDE + kp0 + 4 + t4];
            }
#pragma unroll
            for (int mi = 0; mi < 4; mi++) {
                int m = wm + mi * 16 + gid;
                uint32_t a0 = AsH[m * PSTRIDE + kp0 + t4];
                uint32_t a1 = AsH[(m + 8) * PSTRIDE + kp0 + t4];
                uint32_t a2 = AsH[m * PSTRIDE + kp0 + 4 + t4];
                uint32_t a3 = AsH[(m + 8) * PSTRIDE + kp0 + 4 + t4];
                uint32_t e0 = AsL[m * PSTRIDE + kp0 + t4];
                uint32_t e1 = AsL[(m + 8) * PSTRIDE + kp0 + t4];
                uint32_t e2 = AsL[m * PSTRIDE + kp0 + 4 + t4];
                uint32_t e3 = AsL[(m + 8) * PSTRIDE + kp0 + 4 + t4];
#pragma unroll
                for (int ni = 0; ni < 4; ni++) {
                    mma_bf16(acc[mi][ni], a0, a1, a2, a3, bhf[ni][0], bhf[ni][1]);
                    mma_bf16(acc[mi][ni], a0, a1, a2, a3, blf[ni][0], blf[ni][1]);
                    mma_bf16(acc[mi][ni], e0, e1, e2, e3, bhf[ni][0], bhf[ni][1]);
                }
            }
        }
        __syncthreads();
    }

#pragma unroll
    for (int mi = 0; mi < 4; mi++)
#pragma unroll
        for (int ni = 0; ni < 4; ni++) {
            int row = bm + wm + mi * 16 + gid;
            int col = bn + wn + ni * 8 + t4 * 2;
            *(float2*)&C[(size_t)row * N + col] =
                make_float2(acc[mi][ni][0], acc[mi][ni][1]);
            *(float2*)&C[(size_t)(row + 8) * N + col] =
                make_float2(acc[mi][ni][2], acc[mi][ni][3]);
        }
}

// ---------------- LayerNorm + interleaved RoPE -> Q/K bf16 planes ------------
__global__ __launch_bounds__(128) void norm_rope_kernel(
    const int* __restrict__ positions,
    const float* __restrict__ qw, const float* __restrict__ kw)
{
    int t  = blockIdx.x;
    int hh = blockIdx.y;
    bool is_q = hh < NH;
    int head  = is_q ? hh : hh - NH;
    int base  = t * QKVW + (is_q ? head * HD : NH * HD + head * HD);
    int c = threadIdx.x;

    float x = g_qkv[base + c];

    __shared__ float red[4];
    __shared__ float ybuf[HD];

    float s = x;
#pragma unroll
    for (int o = 16; o; o >>= 1) s += __shfl_xor_sync(0xffffffffu, s, o);
    if ((c & 31) == 0) red[c >> 5] = s;
    __syncthreads();
    float mean = (red[0] + red[1] + red[2] + red[3]) * (1.0f / HD);
    __syncthreads();

    float d  = x - mean;
    float s2 = d * d;
#pragma unroll
    for (int o = 16; o; o >>= 1) s2 += __shfl_xor_sync(0xffffffffu, s2, o);
    if ((c & 31) == 0) red[c >> 5] = s2;
    __syncthreads();
    float var = (red[0] + red[1] + red[2] + red[3]) * (1.0f / HD);

    float w = is_q ? qw[head * HD + c] : kw[head * HD + c];
    ybuf[c] = d * rsqrtf(var + 1e-5f) * w;
    __syncthreads();

    if (c < HD / 2) {
        float x1 = ybuf[2 * c], x2 = ybuf[2 * c + 1];
        float fpos = (float)positions[t];
        float inv_freq = exp2f(-((float)(2 * c) * (1.0f / HD)) * 13.287712379549449f);
        float f = fpos * inv_freq;
        float sn, cs;
        sincosf(f, &sn, &cs);
        float o1 = x1 * cs - x2 * sn;
        float o2 = x2 * cs + x1 * sn;
        uint32_t hh32, ll32;
        if (is_q) {
            split2(o1 * SCALE, o2 * SCALE, hh32, ll32);
            ((uint32_t*)g_qh)[(size_t)t * 2048 + head * 64 + c] = hh32;
            ((uint32_t*)g_ql)[(size_t)t * 2048 + head * 64 + c] = ll32;
        } else {
            split2(o1, o2, hh32, ll32);
            ((uint32_t*)g_kh)[(size_t)t * 512 + head * 64 + c] = hh32;
            ((uint32_t*)g_kl)[(size_t)t * 512 + head * 64 + c] = ll32;
        }
    }
}

// ================= flash attention: reg-P + cp.async double-buffered K/V =====
// BM=128, BN=64, 256 thr = 8 warps; warp owns 16 Q rows; softmax + P in regs.
// smem u32 layout: QH[128*QP] QL[128*QP] | K buf0/buf1 (KH[64*QP] KL[64*QP])
//                  | V buf0/buf1 (VH[128*VP] VL[128*VP])
#define QP 68
#define VP 36
#define FQL_O   (128 * QP)            /* 8704  */
#define FK_O    (2 * 128 * QP)        /* 17408 */
#define FKBUF   (2 * 64 * QP)         /* 8704  */
#define FKL_O   (64 * QP)             /* 4352  */
#define FV_O    (FK_O + 2 * FKBUF)    /* 34816 */
#define FVBUF   (2 * 128 * VP)        /* 9216  */
#define FVL_O   (128 * VP)            /* 4608  */
#define FLASH_U32 (FV_O + 2 * FVBUF)  /* 53248 */
#define FLASH_SMEM (FLASH_U32 * 4)    /* 212992 B */

__global__ __launch_bounds__(256) void flash_mma_kernel()
{
    extern __shared__ uint32_t smu[];

    int qb  = (gridDim.x - 1) - blockIdx.x;   // heavy blocks first
    int h   = blockIdx.y;
    int hkv = h >> 2;
    int tid = threadIdx.x;
    int w   = tid >> 5, lane = tid & 31;
    int gid = lane >> 2, t4 = lane & 3;
    int r0  = w * 16;

    uint32_t smbase = (uint32_t)__cvta_generic_to_shared(smu);

    const uint4* kh4 = (const uint4*)g_kh + ((size_t)hkv * HD) / 8;
    const uint4* kl4 = (const uint4*)g_kl + ((size_t)hkv * HD) / 8;
    const uint4* vh4 = (const uint4*)g_vth + ((size_t)hkv * HD * T) / 8;
    const uint4* vl4 = (const uint4*)g_vtl + ((size_t)hkv * HD * T) / 8;

    // cp.async loader for K/V tile kb2 into buffer kb2&1
    auto load_kv = [&](int kb2) {
        int b = kb2 & 1;
        uint32_t kdst = smbase + (FK_O + b * FKBUF) * 4;
        const uint4* kh = kh4 + (size_t)(kb2 * 64) * 128;   // row stride NKV*HD/8=128
        const uint4* kl = kl4 + (size_t)(kb2 * 64) * 128;
#pragma unroll
        for (int j = 0; j < 4; j++) {
            int idx = tid + 256 * j;               // 1024 chunks: 64 rows x 16 u4
            int r = idx >> 4, u = idx & 15;
            uint32_t d = kdst + (uint32_t)(r * QP + u * 4) * 4;
            cp_async16(d,             kh + r * 128 + u);
            cp_async16(d + FKL_O * 4, kl + r * 128 + u);
        }
        uint32_t vdst = smbase + (FV_O + b * FVBUF) * 4;
        const uint4* vh = vh4 + (size_t)(kb2 * 64) / 8;     // d stride T/8=256
        const uint4* vl = vl4 + (size_t)(kb2 * 64) / 8;
#pragma unroll
        for (int j = 0; j < 4; j++) {
            int idx = tid + 256 * j;               // 1024 chunks: 128 d x 8 u4
            int dd = idx >> 3, u = idx & 7;
            uint32_t d = vdst + (uint32_t)(dd * VP + u * 4) * 4;
            cp_async16(d,             vh + dd * 256 + u);
            cp_async16(d + FVL_O * 4, vl + dd * 256 + u);
        }
        asm volatile("cp.async.commit_group;\n");
    };

    // ---- load Q planes (plain stores) ----
    {
        const uint4* qh4 = (const uint4*)g_qh + ((size_t)(qb * 128) * (NH * HD) + h * HD) / 8;
        const uint4* ql4 = (const uint4*)g_ql + ((size_t)(qb * 128) * (NH * HD) + h * HD) / 8;
        for (int idx = tid; idx < 128 * 16; idx += 256) {
            int r = idx >> 4, u = idx & 15;
            *(uint4*)&smu[r * QP + u * 4]         = qh4[r * 512 + u];
            *(uint4*)&smu[FQL_O + r * QP + u * 4] = ql4[r * 512 + u];
        }
    }

    load_kv(0);   // prologue

    float of[16][4];
#pragma unroll
    for (int ni = 0; ni < 16; ni++)
#pragma unroll
        for (int r = 0; r < 4; r++) of[ni][r] = 0.f;
    float mst0 = -1e30f, mst1 = -1e30f, lst0 = 0.f, lst1 = 0.f;

    int nkb = 2 * qb + 2;
    for (int kb = 0; kb < nkb; kb++) {
        __syncthreads();   // prior reads of buffers (kb+1)&1 complete (+ Q visible)
        if (kb + 1 < nkb) {
            load_kv(kb + 1);
            asm volatile("cp.async.wait_group 1;\n" ::: "memory");
        } else {
            asm volatile("cp.async.wait_group 0;\n" ::: "memory");
        }
        __syncthreads();   // K/V[kb] visible to all

        int b = kb & 1;
        const uint32_t* KHp = smu + FK_O + b * FKBUF;
        const uint32_t* KLp = KHp + FKL_O;
        const uint32_t* VHp = smu + FV_O + b * FVBUF;
        const uint32_t* VLp = VHp + FVL_O;

        // ---- S = Q @ K^T : 8 k16 slabs x 8 n-tiles ----
        float sf[8][4];
#pragma unroll
        for (int ni = 0; ni < 8; ni++)
#pragma unroll
            for (int r = 0; r < 4; r++) sf[ni][r] = 0.f;

#pragma unroll
        for (int ks = 0; ks < 8; ks++) {
            int kp = ks * 8;
            uint32_t a0 = smu[(r0 + gid) * QP + kp + t4];
            uint32_t a1 = smu[(r0 + gid + 8) * QP + kp + t4];
            uint32_t a2 = smu[(r0 + gid) * QP + kp + 4 + t4];
            uint32_t a3 = smu[(r0 + gid + 8) * QP + kp + 4 + t4];
            uint32_t e0 = smu[FQL_O + (r0 + gid) * QP + kp + t4];
            uint32_t e1 = smu[FQL_O + (r0 + gid + 8) * QP + kp + t4];
            uint32_t e2 = smu[FQL_O + (r0 + gid) * QP + kp + 4 + t4];
            uint32_t e3 = smu[FQL_O + (r0 + gid + 8) * QP + kp + 4 + t4];
#pragma unroll
            for (int ni = 0; ni < 8; ni++) {
                int n = ni * 8 + gid;
                uint32_t b0 = KHp[n * QP + kp + t4];
                uint32_t b1 = KHp[n * QP + kp + 4 + t4];
                uint32_t f0 = KLp[n * QP + kp + t4];
                uint32_t f1 = KLp[n * QP + kp + 4 + t4];
                mma_bf16(sf[ni], a0, a1, a2, a3, b0, b1);
                mma_bf16(sf[ni], a0, a1, a2, a3, f0, f1);
                mma_bf16(sf[ni], e0, e1, e2, e3, b0, b1);
            }
        }

        // ---- causal mask ----
        if (kb >= 2 * qb) {
            int R0 = qb * 128 + r0 + gid;
            int R1 = R0 + 8;
            int jb = kb * 64;
#pragma unroll
            for (int ni = 0; ni < 8; ni++) {
                int c0 = jb + ni * 8 + t4 * 2;
                if (c0     > R0) sf[ni][0] = -1e30f;
                if (c0 + 1 > R0) sf[ni][1] = -1e30f;
                if (c0     > R1) sf[ni][2] = -1e30f;
                if (c0 + 1 > R1) sf[ni][3] = -1e30f;
            }
        }

        // ---- online softmax (per-thread rows gid / gid+8) ----
        float mx0 = -1e30f, mx1 = -1e30f;
#pragma unroll
        for (int ni = 0; ni < 8; ni++) {
            mx0 = fmaxf(mx0, fmaxf(sf[ni][0], sf[ni][1]));
            mx1 = fmaxf(mx1, fmaxf(sf[ni][2], sf[ni][3]));
        }
        mx0 = fmaxf(mx0, __shfl_xor_sync(0xffffffffu, mx0, 1));
        mx0 = fmaxf(mx0, __shfl_xor_sync(0xffffffffu, mx0, 2));
        mx1 = fmaxf(mx1, __shfl_xor_sync(0xffffffffu, mx1, 1));
        mx1 = fmaxf(mx1, __shfl_xor_sync(0xffffffffu, mx1, 2));

        float mn0 = fmaxf(mst0, mx0), mn1 = fmaxf(mst1, mx1);
        float a0s = __expf(mst0 - mn0), a1s = __expf(mst1 - mn1);
        mst0 = mn0; mst1 = mn1;

        float ls0 = 0.f, ls1 = 0.f;
#pragma unroll
        for (int ni = 0; ni < 8; ni++) {
            sf[ni][0] = __expf(sf[ni][0] - mn0);
            sf[ni][1] = __expf(sf[ni][1] - mn0);
            sf[ni][2] = __expf(sf[ni][2] - mn1);
            sf[ni][3] = __expf(sf[ni][3] - mn1);
            ls0 += sf[ni][0] + sf[ni][1];
            ls1 += sf[ni][2] + sf[ni][3];
        }
        ls0 += __shfl_xor_sync(0xffffffffu, ls0, 1);
        ls0 += __shfl_xor_sync(0xffffffffu, ls0, 2);
        ls1 += __shfl_xor_sync(0xffffffffu, ls1, 1);
        ls1 += __shfl_xor_sync(0xffffffffu, ls1, 2);
        lst0 = a0s * lst0 + ls0;
        lst1 = a1s * lst1 + ls1;

#pragma unroll
        for (int ni = 0; ni < 16; ni++) {
            of[ni][0] *= a0s; of[ni][1] *= a0s;
            of[ni][2] *= a1s; of[ni][3] *= a1s;
        }

        // ---- O += P @ V : P stays in registers (C-frag == A-frag layout) ----
#pragma unroll
        for (int ks = 0; ks < 4; ks++) {
            int kp = ks * 8;
            uint32_t a0, a1, a2, a3, e0, e1, e2, e3;
            split2(sf[2 * ks][0],     sf[2 * ks][1],     a0, e0);
            split2(sf[2 * ks][2],     sf[2 * ks][3],     a1, e1);
            split2(sf[2 * ks + 1][0], sf[2 * ks + 1][1], a2, e2);
            split2(sf[2 * ks + 1][2], sf[2 * ks + 1][3], a3, e3);
#pragma unroll
            for (int ni = 0; ni < 16; ni++) {
                int n = ni * 8 + gid;
                uint32_t b0 = VHp[n * VP + kp + t4];
                uint32_t b1 = VHp[n * VP + kp + 4 + t4];
                uint32_t f0 = VLp[n * VP + kp + t4];
                uint32_t f1 = VLp[n * VP + kp + 4 + t4];
                mma_bf16(of[ni], a0, a1, a2, a3, b0, b1);
                mma_bf16(of[ni], a0, a1, a2, a3, f0, f1);
                mma_bf16(of[ni], e0, e1, e2, e3, b0, b1);
            }
        }
    }

    // ---- epilogue: write attn output directly as A hi/lo planes ----
    float li0 = 1.0f / lst0, li1 = 1.0f / lst1;
    int R0 = qb * 128 + r0 + gid;
    int R1 = R0 + 8;
    uint32_t* pah = (uint32_t*)g_ah;
    uint32_t* pal = (uint32_t*)g_al;
#pragma unroll
    for (int ni = 0; ni < 16; ni++) {
        int colp = h * 64 + ni * 4 + t4;
        uint32_t hh32, ll32;
        split2(of[ni][0] * li0, of[ni][1] * li0, hh32, ll32);
        pah[(size_t)R0 * 2048 + colp] = hh32;
        pal[(size_t)R0 * 2048 + colp] = ll32;
        split2(of[ni][2] * li1, of[ni][3] * li1, hh32, ll32);
        pah[(size_t)R1 * 2048 + colp] = hh32;
        pal[(size_t)R1 * 2048 + colp] = ll32;
    }
}

// ---------------- launch ----------------
extern "C" void kernel_launch(void* const* d_in, const int* in_sizes, int n_in,
                              void* d_out, int out_size)
{
    const int*   positions = (const int*)d_in[0];
    const float* hidden    = (const float*)d_in[1];
    const float* w_qkv     = (const float*)d_in[2];
    const float* w_o       = (const float*)d_in[3];
    const float* qw        = (const float*)d_in[4];
    const float* kw        = (const float*)d_in[5];
    float*       out       = (float*)d_out;

    float* qkvp;
    __nv_bfloat16 *ahp, *alp, *bhp, *blp;
    cudaGetSymbolAddress((void**)&qkvp, g_qkv);
    cudaGetSymbolAddress((void**)&ahp, g_ah);
    cudaGetSymbolAddress((void**)&alp, g_al);
    cudaGetSymbolAddress((void**)&bhp, g_bh);
    cudaGetSymbolAddress((void**)&blp, g_bl);

    cudaFuncSetAttribute(gemm_planes,
                         cudaFuncAttributeMaxDynamicSharedMemorySize, GEMM_SMEM);
    cudaFuncSetAttribute(flash_mma_kernel,
                         cudaFuncAttributeMaxDynamicSharedMemorySize, FLASH_SMEM);

    // 1) split hidden -> A planes; split+transpose w_qkv -> B planes
    split_plane<<<4096, 256>>>((const float2*)hidden,
                               (uint32_t*)ahp, (uint32_t*)alp, T * H / 2);
    split_transpose<<<dim3(QKVW / 32, H / 32), dim3(32, 8)>>>(w_qkv, bhp, blp, H, QKVW);

    // 2) QKV projection (bf16x3 HMMA)
    gemm_planes<<<dim3(QKVW / 128, T / 128), 256, GEMM_SMEM>>>(
        ahp, alp, bhp, blp, qkvp, T, QKVW, H);

    // 3) LayerNorm + RoPE -> Q/K planes; V -> transposed planes
    norm_rope_kernel<<<dim3(T, NH + NKV), 128>>>(positions, qw, kw);
    split_transpose_v<<<dim3(T / 32, HD / 32, NKV), dim3(32, 8)>>>();

    // 4) flash attention -> writes A planes directly
    flash_mma_kernel<<<dim3(T / 128, NH), 256, FLASH_SMEM>>>();

    // 5) split+transpose w_o -> B planes; output projection
    split_transpose<<<dim3(H / 32, (NH * HD) / 32), dim3(32, 8)>>>(w_o, bhp, blp, NH * HD, H);
    gemm_planes<<<dim3(H / 128, T / 128), 256, GEMM_SMEM>>>(
        ahp, alp, bhp, blp, out, T, H, NH * HD);
}

// round 14
// speedup vs baseline: 1.1592x; 1.0097x over previous
#include <cuda_runtime.h>
#include <cuda_bf16.h>
#include <math.h>
#include <stdint.h>

#define T 2048
#define H 4096
#define NH 32
#define NKV 8
#define HD 128
#define QKVW ((NH + 2 * NKV) * HD)   /* 6144 */
#define SCALE 0.08838834764831845f   /* HD^-0.5 */

// ---------------- scratch (static device memory; no allocs allowed) ----------
__device__ float g_qkv[T * QKVW];                                  // fp32 QKV
__device__ __align__(256) __nv_bfloat16 g_ah[T * H],      g_al[T * H];        // A planes
__device__ __align__(256) __nv_bfloat16 g_bh[H * QKVW],   g_bl[H * QKVW];     // B planes ([N][K])
__device__ __align__(256) __nv_bfloat16 g_qh[T * NH * HD], g_ql[T * NH * HD];
__device__ __align__(256) __nv_bfloat16 g_kh[T * NKV * HD], g_kl[T * NKV * HD];
__device__ __align__(256) __nv_bfloat16 g_vth[NKV * HD * T], g_vtl[NKV * HD * T]; // V^T [hkv][d][t]

// ================= helpers ================
__device__ __forceinline__ void mma_bf16(float c[4],
    uint32_t a0, uint32_t a1, uint32_t a2, uint32_t a3,
    uint32_t b0, uint32_t b1)
{
    asm volatile(
        "mma.sync.aligned.m16n8k16.row.col.f32.bf16.bf16.f32 "
        "{%0,%1,%2,%3},{%4,%5,%6,%7},{%8,%9},{%0,%1,%2,%3};\n"
        : "+f"(c[0]), "+f"(c[1]), "+f"(c[2]), "+f"(c[3])
        : "r"(a0), "r"(a1), "r"(a2), "r"(a3), "r"(b0), "r"(b1));
}

__device__ __forceinline__ uint32_t pack_hi16(float x0, float x1)
{
    uint32_t r;
    asm("prmt.b32 %0, %1, %2, 0x7632;"
        : "=r"(r) : "r"(__float_as_uint(x0)), "r"(__float_as_uint(x1)));
    return r;
}

__device__ __forceinline__ void split2(float x0, float x1, uint32_t& h, uint32_t& l)
{
    h = pack_hi16(x0, x1);
    float l0 = x0 - __uint_as_float(__float_as_uint(x0) & 0xffff0000u);
    float l1 = x1 - __uint_as_float(__float_as_uint(x1) & 0xffff0000u);
    l = pack_hi16(l0, l1);
}

__device__ __forceinline__ void split1(float v, uint16_t& h16, uint16_t& l16)
{
    uint32_t u = __float_as_uint(v);
    h16 = (uint16_t)(u >> 16);
    float lo = v - __uint_as_float(u & 0xffff0000u);
    l16 = (uint16_t)(__float_as_uint(lo) >> 16);
}

__device__ __forceinline__ void cp_async16(uint32_t dst, const void* src)
{
    asm volatile("cp.async.cg.shared.global [%0], [%1], 16;\n"
                 :: "r"(dst), "l"(src));
}

// ================= prep kernels ================
__global__ void split_plane(const float2* __restrict__ in,
    uint32_t* __restrict__ hi, uint32_t* __restrict__ lo, int npairs)
{
    for (int i = blockIdx.x * blockDim.x + threadIdx.x; i < npairs;
         i += gridDim.x * blockDim.x) {
        float2 v = in[i];
        uint32_t h, l;
        split2(v.x, v.y, h, l);
        hi[i] = h; lo[i] = l;
    }
}

__global__ void split_transpose(const float* __restrict__ B,
    __nv_bfloat16* __restrict__ Bth, __nv_bfloat16* __restrict__ Btl,
    int K, int N)
{
    __shared__ float tile[32][33];
    int n0 = blockIdx.x * 32, k0 = blockIdx.y * 32;
    int tx = threadIdx.x, ty = threadIdx.y;
#pragma unroll
    for (int i = 0; i < 4; i++)
        tile[ty + 8 * i][tx] = B[(size_t)(k0 + ty + 8 * i) * N + n0 + tx];
    __syncthreads();
#pragma unroll
    for (int i = 0; i < 4; i++) {
        float v = tile[tx][ty + 8 * i];
        uint16_t h16, l16;
        split1(v, h16, l16);
        size_t o = (size_t)(n0 + ty + 8 * i) * K + k0 + tx;
        ((uint16_t*)Bth)[o] = h16;
        ((uint16_t*)Btl)[o] = l16;
    }
}

__global__ void split_transpose_v()
{
    __shared__ float tile[32][33];
    int t0 = blockIdx.x * 32, d0 = blockIdx.y * 32, hkv = blockIdx.z;
    int tx = threadIdx.x, ty = threadIdx.y;
#pragma unroll
    for (int i = 0; i < 4; i++)
        tile[ty + 8 * i][tx] =
            g_qkv[(size_t)(t0 + ty + 8 * i) * QKVW + (NH + NKV) * HD + hkv * HD + d0 + tx];
    __syncthreads();
#pragma unroll
    for (int i = 0; i < 4; i++) {
        float v = tile[tx][ty + 8 * i];
        uint16_t h16, l16;
        split1(v, h16, l16);
        size_t o = (size_t)hkv * HD * T + (size_t)(d0 + ty + 8 * i) * T + t0 + tx;
        ((uint16_t*)g_vth)[o] = h16;
        ((uint16_t*)g_vtl)[o] = l16;
    }
}

// ================= plane GEMM: pure HMMA mainloop + L2 CTA swizzle ==========
#define PSTRIDE 20                    /* uint32 pairs per row: 16 data + 4 pad */
#define TILE_U32 (128 * PSTRIDE)      /* 2560 */
#define STAGE_U32 (4 * TILE_U32)      /* AsH AsL BsH BsL */
#define GEMM_SMEM (2 * STAGE_U32 * 4) /* 81920 B */
#define GEMM_GW 8                     /* column-group width for L2 reuse */

__global__ __launch_bounds__(256, 2) void gemm_planes(
    const __nv_bfloat16* __restrict__ Ah, const __nv_bfloat16* __restrict__ Al,
    const __nv_bfloat16* __restrict__ Bh, const __nv_bfloat16* __restrict__ Bl,
    float* __restrict__ C, int M, int N, int K)
{
    extern __shared__ uint32_t smu[];
    int tid  = threadIdx.x;
    int warp = tid >> 5, lane = tid & 31;
    int gid  = lane >> 2, t4 = lane & 3;
    int wm   = (warp >> 2) * 64;
    int wn   = (warp & 3) * 32;

    // grouped CTA raster: consecutive CTAs sweep all bm within an 8-wide bn group
    // (keeps one B slab resident in L2; gridDim.x must be divisible by GEMM_GW)
    int lin   = blockIdx.y * gridDim.x + blockIdx.x;
    int gsz   = GEMM_GW * gridDim.y;
    int grp   = lin / gsz;
    int rem   = lin - grp * gsz;
    int bm    = (rem / GEMM_GW) * 128;
    int bn    = (grp * GEMM_GW + (rem % GEMM_GW)) * 128;

    float acc[4][4][4];
#pragma unroll
    for (int mi = 0; mi < 4; mi++)
#pragma unroll
        for (int ni = 0; ni < 4; ni++)
#pragma unroll
            for (int r = 0; r < 4; r++) acc[mi][ni][r] = 0.f;

    uint32_t smbase = (uint32_t)__cvta_generic_to_shared(smu);
    int lr = tid >> 2;     // 0..63
    int lc = tid & 3;      // 16B chunk within 64B row

    auto load_stage = [&](int s, int kt) {
        uint32_t base = smbase + s * STAGE_U32 * 4;
#pragma unroll
        for (int half = 0; half < 2; half++) {
            int r = lr + 64 * half;
            uint32_t d = base + (r * PSTRIDE + lc * 4) * 4;
            cp_async16(d,                    Ah + (size_t)(bm + r) * K + kt + lc * 8);
            cp_async16(d + TILE_U32 * 4,     Al + (size_t)(bm + r) * K + kt + lc * 8);
            cp_async16(d + 2 * TILE_U32 * 4, Bh + (size_t)(bn + r) * K + kt + lc * 8);
            cp_async16(d + 3 * TILE_U32 * 4, Bl + (size_t)(bn + r) * K + kt + lc * 8);
        }
        asm volatile("cp.async.commit_group;\n");
    };

    load_stage(0, 0);
    int niter = K >> 5;

    for (int it = 0; it < niter; it++) {
        int s = it & 1;
        if (it + 1 < niter) {
            load_stage(s ^ 1, (it + 1) << 5);
            asm volatile("cp.async.wait_group 1;\n");
        } else {
            asm volatile("cp.async.wait_group 0;\n");
        }
        __syncthreads();

        const uint32_t* AsH = smu + s * STAGE_U32;
        const uint32_t* AsL = AsH + TILE_U32;
        const uint32_t* BsH = AsH + 2 * TILE_U32;
        const uint32_t* BsL = AsH + 3 * TILE_U32;

#pragma unroll
        for (int kp0 = 0; kp0 < 16; kp0 += 8) {
            uint32_t bhf[4][2], blf[4][2];
#pragma unroll
            for (int ni = 0; ni < 4; ni++) {
                int n = wn + ni * 8 + gid;
                bhf[ni][0] = BsH[n * PSTRIDE + kp0 + t4];
                bhf[ni][1] = BsH[n * PSTRIDE + kp0 + 4 + t4];
                blf[ni][0] = BsL[n * PSTRIDE + kp0 + t4];
                blf[ni][1] = BsL[n * PSTRIDE + kp0 + 4 + t4];
            }
#pragma unroll
            for (int mi = 0; mi < 4; mi++) {
                int m = wm + mi * 16 + gid;
                uint32_t a0 = AsH[m * PSTRIDE + kp0 + t4];
                uint32_t a1 = AsH[(m + 8) * PSTRIDE + kp0 + t4];
                uint32_t a2 = AsH[m * PSTRIDE + kp0 + 4 + t4];
                uint32_t a3 = AsH[(m + 8) * PSTRIDE + kp0 + 4 + t4];
                uint32_t e0 = AsL[m * PSTRIDE + kp0 + t4];
                uint32_t e1 = AsL[(m + 8) * PSTRIDE + kp0 + t4];
                uint32_t e2 = AsL[m * PSTRIDE + kp0 + 4 + t4];
                uint32_t e3 = AsL[(m + 8) * PSTRIDE + kp0 + 4 + t4];
#pragma unroll
                for (int ni = 0; ni < 4; ni++) {
                    mma_bf16(acc[mi][ni], a0, a1, a2, a3, bhf[ni][0], bhf[ni][1]);
                    mma_bf16(acc[mi][ni], a0, a1, a2, a3, blf[ni][0], blf[ni][1]);
                    mma_bf16(acc[mi][ni], e0, e1, e2, e3, bhf[ni][0], bhf[ni][1]);
                }
            }
        }
        __syncthreads();
    }

#pragma unroll
    for (int mi = 0; mi < 4; mi++)
#pragma unroll
        for (int ni = 0; ni < 4; ni++) {
            int row = bm + wm + mi * 16 + gid;
            int col = bn + wn + ni * 8 + t4 * 2;
            *(float2*)&C[(size_t)row * N + col] =
                make_float2(acc[mi][ni][0], acc[mi][ni][1]);
            *(float2*)&C[(size_t)(row + 8) * N + col] =
                make_float2(acc[mi][ni][2], acc[mi][ni][3]);
        }
}

// -------- LayerNorm + interleaved RoPE, warp-per-head (no smem/barriers) -----
// grid (T, 10), 128 thr = 4 warps; warp w handles head hh = by*4+w (0..39).
__global__ __launch_bounds__(128) void norm_rope_kernel(
    const int* __restrict__ positions,
    const float* __restrict__ qw, const float* __restrict__ kw)
{
    int t    = blockIdx.x;
    int w    = threadIdx.x >> 5, lane = threadIdx.x & 31;
    int hh   = blockIdx.y * 4 + w;
    bool is_q = hh < NH;
    int head = is_q ? hh : hh - NH;

    const float* src = &g_qkv[(size_t)t * QKVW + (is_q ? head * HD : NH * HD + head * HD)];
    float4 x = *(const float4*)&src[lane * 4];

    float s = x.x + x.y + x.z + x.w;
#pragma unroll
    for (int o = 16; o; o >>= 1) s += __shfl_xor_sync(0xffffffffu, s, o);
    float mean = s * (1.0f / HD);

    float d0 = x.x - mean, d1 = x.y - mean, d2 = x.z - mean, d3 = x.w - mean;
    float s2 = d0 * d0 + d1 * d1 + d2 * d2 + d3 * d3;
#pragma unroll
    for (int o = 16; o; o >>= 1) s2 += __shfl_xor_sync(0xffffffffu, s2, o);
    float rstd = rsqrtf(s2 * (1.0f / HD) + 1e-5f);

    const float* wp = is_q ? &qw[head * HD] : &kw[head * HD];
    float4 wv = *(const float4*)&wp[lane * 4];
    float y[4] = { d0 * rstd * wv.x, d1 * rstd * wv.y,
                   d2 * rstd * wv.z, d3 * rstd * wv.w };

    float fpos = (float)positions[t];
#pragma unroll
    for (int j = 0; j < 2; j++) {
        int p = lane * 2 + j;            // pair index within head (0..63)
        float inv_freq = exp2f(-((float)(2 * p) * (1.0f / HD)) * 13.287712379549449f);
        float f = fpos * inv_freq;
        float sn, cs;
        sincosf(f, &sn, &cs);
        float x1 = y[2 * j], x2 = y[2 * j + 1];
        float o1 = x1 * cs - x2 * sn;
        float o2 = x2 * cs + x1 * sn;
        uint32_t hh32, ll32;
        if (is_q) {
            split2(o1 * SCALE, o2 * SCALE, hh32, ll32);
            ((uint32_t*)g_qh)[(size_t)t * 2048 + head * 64 + p] = hh32;
            ((uint32_t*)g_ql)[(size_t)t * 2048 + head * 64 + p] = ll32;
        } else {
            split2(o1, o2, hh32, ll32);
            ((uint32_t*)g_kh)[(size_t)t * 512 + head * 64 + p] = hh32;
            ((uint32_t*)g_kl)[(size_t)t * 512 + head * 64 + p] = ll32;
        }
    }
}

// ================= flash attention: reg-P + cp.async double-buffered K/V =====
#define QP 68
#define VP 36
#define FQL_O   (128 * QP)
#define FK_O    (2 * 128 * QP)
#define FKBUF   (2 * 64 * QP)
#define FKL_O   (64 * QP)
#define FV_O    (FK_O + 2 * FKBUF)
#define FVBUF   (2 * 128 * VP)
#define FVL_O   (128 * VP)
#define FLASH_U32 (FV_O + 2 * FVBUF)
#define FLASH_SMEM (FLASH_U32 * 4)    /* 212992 B */

__global__ __launch_bounds__(256) void flash_mma_kernel()
{
    extern __shared__ uint32_t smu[];

    int qb  = (gridDim.x - 1) - blockIdx.x;   // heavy blocks first
    int h   = blockIdx.y;
    int hkv = h >> 2;
    int tid = threadIdx.x;
    int w   = tid >> 5, lane = tid & 31;
    int gid = lane >> 2, t4 = lane & 3;
    int r0  = w * 16;

    uint32_t smbase = (uint32_t)__cvta_generic_to_shared(smu);

    const uint4* kh4 = (const uint4*)g_kh + ((size_t)hkv * HD) / 8;
    const uint4* kl4 = (const uint4*)g_kl + ((size_t)hkv * HD) / 8;
    const uint4* vh4 = (const uint4*)g_vth + ((size_t)hkv * HD * T) / 8;
    const uint4* vl4 = (const uint4*)g_vtl + ((size_t)hkv * HD * T) / 8;

    auto load_kv = [&](int kb2) {
        int b = kb2 & 1;
        uint32_t kdst = smbase + (FK_O + b * FKBUF) * 4;
        const uint4* kh = kh4 + (size_t)(kb2 * 64) * 128;
        const uint4* kl = kl4 + (size_t)(kb2 * 64) * 128;
#pragma unroll
        for (int j = 0; j < 4; j++) {
            int idx = tid + 256 * j;
            int r = idx >> 4, u = idx & 15;
            uint32_t d = kdst + (uint32_t)(r * QP + u * 4) * 4;
            cp_async16(d,             kh + r * 128 + u);
            cp_async16(d + FKL_O * 4, kl + r * 128 + u);
        }
        uint32_t vdst = smbase + (FV_O + b * FVBUF) * 4;
        const uint4* vh = vh4 + (size_t)(kb2 * 64) / 8;
        const uint4* vl = vl4 + (size_t)(kb2 * 64) / 8;
#pragma unroll
        for (int j = 0; j < 4; j++) {
            int idx = tid + 256 * j;
            int dd = idx >> 3, u = idx & 7;
            uint32_t d = vdst + (uint32_t)(dd * VP + u * 4) * 4;
            cp_async16(d,             vh + dd * 256 + u);
            cp_async16(d + FVL_O * 4, vl + dd * 256 + u);
        }
        asm volatile("cp.async.commit_group;\n");
    };

    {
        const uint4* qh4 = (const uint4*)g_qh + ((size_t)(qb * 128) * (NH * HD) + h * HD) / 8;
        const uint4* ql4 = (const uint4*)g_ql + ((size_t)(qb * 128) * (NH * HD) + h * HD) / 8;
        for (int idx = tid; idx < 128 * 16; idx += 256) {
            int r = idx >> 4, u = idx & 15;
            *(uint4*)&smu[r * QP + u * 4]         = qh4[r * 512 + u];
            *(uint4*)&smu[FQL_O + r * QP + u * 4] = ql4[r * 512 + u];
        }
    }

    load_kv(0);

    float of[16][4];
#pragma unroll
    for (int ni = 0; ni < 16; ni++)
#pragma unroll
        for (int r = 0; r < 4; r++) of[ni][r] = 0.f;
    float mst0 = -1e30f, mst1 = -1e30f, lst0 = 0.f, lst1 = 0.f;

    int nkb = 2 * qb + 2;
    for (int kb = 0; kb < nkb; kb++) {
        __syncthreads();
        if (kb + 1 < nkb) {
            load_kv(kb + 1);
            asm volatile("cp.async.wait_group 1;\n" ::: "memory");
        } else {
            asm volatile("cp.async.wait_group 0;\n" ::: "memory");
        }
        __syncthreads();

        int b = kb & 1;
        const uint32_t* KHp = smu + FK_O + b * FKBUF;
        const uint32_t* KLp = KHp + FKL_O;
        const uint32_t* VHp = smu + FV_O + b * FVBUF;
        const uint32_t* VLp = VHp + FVL_O;

        float sf[8][4];
#pragma unroll
        for (int ni = 0; ni < 8; ni++)
#pragma unroll
            for (int r = 0; r < 4; r++) sf[ni][r] = 0.f;

#pragma unroll
        for (int ks = 0; ks < 8; ks++) {
            int kp = ks * 8;
            uint32_t a0 = smu[(r0 + gid) * QP + kp + t4];
            uint32_t a1 = smu[(r0 + gid + 8) * QP + kp + t4];
            uint32_t a2 = smu[(r0 + gid) * QP + kp + 4 + t4];
            uint32_t a3 = smu[(r0 + gid + 8) * QP + kp + 4 + t4];
            uint32_t e0 = smu[FQL_O + (r0 + gid) * QP + kp + t4];
            uint32_t e1 = smu[FQL_O + (r0 + gid + 8) * QP + kp + t4];
            uint32_t e2 = smu[FQL_O + (r0 + gid) * QP + kp + 4 + t4];
            uint32_t e3 = smu[FQL_O + (r0 + gid + 8) * QP + kp + 4 + t4];
#pragma unroll
            for (int ni = 0; ni < 8; ni++) {
                int n = ni * 8 + gid;
                uint32_t b0 = KHp[n * QP + kp + t4];
                uint32_t b1 = KHp[n * QP + kp + 4 + t4];
                uint32_t f0 = KLp[n * QP + kp + t4];
                uint32_t f1 = KLp[n * QP + kp + 4 + t4];
                mma_bf16(sf[ni], a0, a1, a2, a3, b0, b1);
                mma_bf16(sf[ni], a0, a1, a2, a3, f0, f1);
                mma_bf16(sf[ni], e0, e1, e2, e3, b0, b1);
            }
        }

        if (kb >= 2 * qb) {
            int R0 = qb * 128 + r0 + gid;
            int R1 = R0 + 8;
            int jb = kb * 64;
#pragma unroll
            for (int ni = 0; ni < 8; ni++) {
                int c0 = jb + ni * 8 + t4 * 2;
                if (c0     > R0) sf[ni][0] = -1e30f;
                if (c0 + 1 > R0) sf[ni][1] = -1e30f;
                if (c0     > R1) sf[ni][2] = -1e30f;
                if (c0 + 1 > R1) sf[ni][3] = -1e30f;
            }
        }

        float mx0 = -1e30f, mx1 = -1e30f;
#pragma unroll
        for (int ni = 0; ni < 8; ni++) {
            mx0 = fmaxf(mx0, fmaxf(sf[ni][0], sf[ni][1]));
            mx1 = fmaxf(mx1, fmaxf(sf[ni][2], sf[ni][3]));
        }
        mx0 = fmaxf(mx0, __shfl_xor_sync(0xffffffffu, mx0, 1));
        mx0 = fmaxf(mx0, __shfl_xor_sync(0xffffffffu, mx0, 2));
        mx1 = fmaxf(mx1, __shfl_xor_sync(0xffffffffu, mx1, 1));
        mx1 = fmaxf(mx1, __shfl_xor_sync(0xffffffffu, mx1, 2));

        float mn0 = fmaxf(mst0, mx0), mn1 = fmaxf(mst1, mx1);
        float a0s = __expf(mst0 - mn0), a1s = __expf(mst1 - mn1);
        mst0 = mn0; mst1 = mn1;

        float ls0 = 0.f, ls1 = 0.f;
#pragma unroll
        for (int ni = 0; ni < 8; ni++) {
            sf[ni][0] = __expf(sf[ni][0] - mn0);
            sf[ni][1] = __expf(sf[ni][1] - mn0);
            sf[ni][2] = __expf(sf[ni][2] - mn1);
            sf[ni][3] = __expf(sf[ni][3] - mn1);
            ls0 += sf[ni][0] + sf[ni][1];
            ls1 += sf[ni][2] + sf[ni][3];
        }
        ls0 += __shfl_xor_sync(0xffffffffu, ls0, 1);
        ls0 += __shfl_xor_sync(0xffffffffu, ls0, 2);
        ls1 += __shfl_xor_sync(0xffffffffu, ls1, 1);
        ls1 += __shfl_xor_sync(0xffffffffu, ls1, 2);
        lst0 = a0s * lst0 + ls0;
        lst1 = a1s * lst1 + ls1;

#pragma unroll
        for (int ni = 0; ni < 16; ni++) {
            of[ni][0] *= a0s; of[ni][1] *= a0s;
            of[ni][2] *= a1s; of[ni][3] *= a1s;
        }

#pragma unroll
        for (int ks = 0; ks < 4; ks++) {
            int kp = ks * 8;
            uint32_t a0, a1, a2, a3, e0, e1, e2, e3;
            split2(sf[2 * ks][0],     sf[2 * ks][1],     a0, e0);
            split2(sf[2 * ks][2],     sf[2 * ks][3],     a1, e1);
            split2(sf[2 * ks + 1][0], sf[2 * ks + 1][1], a2, e2);
            split2(sf[2 * ks + 1][2], sf[2 * ks + 1][3], a3, e3);
#pragma unroll
            for (int ni = 0; ni < 16; ni++) {
                int n = ni * 8 + gid;
                uint32_t b0 = VHp[n * VP + kp + t4];
                uint32_t b1 = VHp[n * VP + kp + 4 + t4];
                uint32_t f0 = VLp[n * VP + kp + t4];
                uint32_t f1 = VLp[n * VP + kp + 4 + t4];
                mma_bf16(of[ni], a0, a1, a2, a3, b0, b1);
                mma_bf16(of[ni], a0, a1, a2, a3, f0, f1);
                mma_bf16(of[ni], e0, e1, e2, e3, b0, b1);
            }
        }
    }

    float li0 = 1.0f / lst0, li1 = 1.0f / lst1;
    int R0 = qb * 128 + r0 + gid;
    int R1 = R0 + 8;
    uint32_t* pah = (uint32_t*)g_ah;
    uint32_t* pal = (uint32_t*)g_al;
#pragma unroll
    for (int ni = 0; ni < 16; ni++) {
        int colp = h * 64 + ni * 4 + t4;
        uint32_t hh32, ll32;
        split2(of[ni][0] * li0, of[ni][1] * li0, hh32, ll32);
        pah[(size_t)R0 * 2048 + colp] = hh32;
        pal[(size_t)R0 * 2048 + colp] = ll32;
        split2(of[ni][2] * li1, of[ni][3] * li1, hh32, ll32);
        pah[(size_t)R1 * 2048 + colp] = hh32;
        pal[(size_t)R1 * 2048 + colp] = ll32;
    }
}

// ---------------- launch ----------------
extern "C" void kernel_launch(void* const* d_in, const int* in_sizes, int n_in,
                              void* d_out, int out_size)
{
    const int*   positions = (const int*)d_in[0];
    const float* hidden    = (const float*)d_in[1];
    const float* w_qkv     = (const float*)d_in[2];
    const float* w_o       = (const float*)d_in[3];
    const float* qw        = (const float*)d_in[4];
    const float* kw        = (const float*)d_in[5];
    float*       out       = (float*)d_out;

    float* qkvp;
    __nv_bfloat16 *ahp, *alp, *bhp, *blp;
    cudaGetSymbolAddress((void**)&qkvp, g_qkv);
    cudaGetSymbolAddress((void**)&ahp, g_ah);
    cudaGetSymbolAddress((void**)&alp, g_al);
    cudaGetSymbolAddress((void**)&bhp, g_bh);
    cudaGetSymbolAddress((void**)&blp, g_bl);

    cudaFuncSetAttribute(gemm_planes,
                         cudaFuncAttributeMaxDynamicSharedMemorySize, GEMM_SMEM);
    cudaFuncSetAttribute(flash_mma_kernel,
                         cudaFuncAttributeMaxDynamicSharedMemorySize, FLASH_SMEM);

    // 1) split hidden -> A planes; split+transpose w_qkv -> B planes
    split_plane<<<4096, 256>>>((const float2*)hidden,
                               (uint32_t*)ahp, (uint32_t*)alp, T * H / 2);
    split_transpose<<<dim3(QKVW / 32, H / 32), dim3(32, 8)>>>(w_qkv, bhp, blp, H, QKVW);

    // 2) QKV projection (bf16x3 HMMA, L2-swizzled raster)
    gemm_planes<<<dim3(QKVW / 128, T / 128), 256, GEMM_SMEM>>>(
        ahp, alp, bhp, blp, qkvp, T, QKVW, H);

    // 3) LayerNorm + RoPE (warp-per-head) -> Q/K planes; V -> transposed planes
    norm_rope_kernel<<<dim3(T, (NH + NKV) / 4), 128>>>(positions, qw, kw);
    split_transpose_v<<<dim3(T / 32, HD / 32, NKV), dim3(32, 8)>>>();

    // 4) flash attention -> writes A planes directly
    flash_mma_kernel<<<dim3(T / 128, NH), 256, FLASH_SMEM>>>();

    // 5) split+transpose w_o -> B planes; output projection
    split_transpose<<<dim3(H / 32, (NH * HD) / 32), dim3(32, 8)>>>(w_o, bhp, blp, NH * HD, H);
    gemm_planes<<<dim3(H / 128, T / 128), 256, GEMM_SMEM>>>(
        ahp, alp, bhp, blp, out, T, H, NH * HD);
}

// round 15
// speedup vs baseline: 1.1973x; 1.0329x over previous
#include <cuda_runtime.h>
#include <cuda_bf16.h>
#include <math.h>
#include <stdint.h>

#define T 2048
#define H 4096
#define NH 32
#define NKV 8
#define HD 128
#define QKVW ((NH + 2 * NKV) * HD)   /* 6144 */
#define SCALE 0.08838834764831845f   /* HD^-0.5 */

// ---------------- scratch (static device memory; no allocs allowed) ----------
__device__ float g_qkv[T * QKVW];                                  // fp32 QKV
__device__ __align__(256) __nv_bfloat16 g_ah[T * H],      g_al[T * H];        // A planes (k-permuted)
__device__ __align__(256) __nv_bfloat16 g_bh[H * QKVW],   g_bl[H * QKVW];     // B planes ([N][K], k-permuted)
__device__ __align__(256) __nv_bfloat16 g_qh[T * NH * HD], g_ql[T * NH * HD]; // flash planes (natural order)
__device__ __align__(256) __nv_bfloat16 g_kh[T * NKV * HD], g_kl[T * NKV * HD];
__device__ __align__(256) __nv_bfloat16 g_vth[NKV * HD * T], g_vtl[NKV * HD * T]; // V^T [hkv][d][t]

// ================= helpers ================
__device__ __forceinline__ void mma_bf16(float c[4],
    uint32_t a0, uint32_t a1, uint32_t a2, uint32_t a3,
    uint32_t b0, uint32_t b1)
{
    asm volatile(
        "mma.sync.aligned.m16n8k16.row.col.f32.bf16.bf16.f32 "
        "{%0,%1,%2,%3},{%4,%5,%6,%7},{%8,%9},{%0,%1,%2,%3};\n"
        : "+f"(c[0]), "+f"(c[1]), "+f"(c[2]), "+f"(c[3])
        : "r"(a0), "r"(a1), "r"(a2), "r"(a3), "r"(b0), "r"(b1));
}

__device__ __forceinline__ uint32_t pack_hi16(float x0, float x1)
{
    uint32_t r;
    asm("prmt.b32 %0, %1, %2, 0x7632;"
        : "=r"(r) : "r"(__float_as_uint(x0)), "r"(__float_as_uint(x1)));
    return r;
}

__device__ __forceinline__ void split2(float x0, float x1, uint32_t& h, uint32_t& l)
{
    h = pack_hi16(x0, x1);
    float l0 = x0 - __uint_as_float(__float_as_uint(x0) & 0xffff0000u);
    float l1 = x1 - __uint_as_float(__float_as_uint(x1) & 0xffff0000u);
    l = pack_hi16(l0, l1);
}

__device__ __forceinline__ void split1(float v, uint16_t& h16, uint16_t& l16)
{
    uint32_t u = __float_as_uint(v);
    h16 = (uint16_t)(u >> 16);
    float lo = v - __uint_as_float(u & 0xffff0000u);
    l16 = (uint16_t)(__float_as_uint(lo) >> 16);
}

__device__ __forceinline__ void cp_async16(uint32_t dst, const void* src)
{
    asm volatile("cp.async.cg.shared.global [%0], [%1], 16;\n"
                 :: "r"(dst), "l"(src));
}

// k-pair permutation within each k16 group (8 bf16 pairs):
// slot(p) = ((p&3)<<1)|(p>>2) -> frag pairs (t4, t4+4) become adjacent u64.
__device__ __forceinline__ int perm_pair(int p) { return ((p & 3) << 1) | (p >> 2); }
__device__ __forceinline__ int perm_elem(int k)
{
    int p = (k >> 1) & 7;
    return (k & ~15) | (perm_pair(p) << 1) | (k & 1);
}

// ================= prep kernels ================
// elementwise split (pair-granular) with k-pair permutation
__global__ void split_plane(const float2* __restrict__ in,
    uint32_t* __restrict__ hi, uint32_t* __restrict__ lo, int npairs)
{
    for (int i = blockIdx.x * blockDim.x + threadIdx.x; i < npairs;
         i += gridDim.x * blockDim.x) {
        float2 v = in[i];
        uint32_t h, l;
        split2(v.x, v.y, h, l);
        int o = (i & ~7) | perm_pair(i & 7);
        hi[o] = h; lo[o] = l;
    }
}

// B[K][N] fp32 -> Bt hi/lo bf16 [N][K] with k-element permutation
__global__ void split_transpose(const float* __restrict__ B,
    __nv_bfloat16* __restrict__ Bth, __nv_bfloat16* __restrict__ Btl,
    int K, int N)
{
    __shared__ float tile[32][33];
    int n0 = blockIdx.x * 32, k0 = blockIdx.y * 32;
    int tx = threadIdx.x, ty = threadIdx.y;
#pragma unroll
    for (int i = 0; i < 4; i++)
        tile[ty + 8 * i][tx] = B[(size_t)(k0 + ty + 8 * i) * N + n0 + tx];
    __syncthreads();
    int kp = perm_elem(k0 + tx);
#pragma unroll
    for (int i = 0; i < 4; i++) {
        float v = tile[tx][ty + 8 * i];
        uint16_t h16, l16;
        split1(v, h16, l16);
        size_t o = (size_t)(n0 + ty + 8 * i) * K + kp;
        ((uint16_t*)Bth)[o] = h16;
        ((uint16_t*)Btl)[o] = l16;
    }
}

// V region of g_qkv -> V^T planes [hkv][d][t]  (flash-side, natural order)
__global__ void split_transpose_v()
{
    __shared__ float tile[32][33];
    int t0 = blockIdx.x * 32, d0 = blockIdx.y * 32, hkv = blockIdx.z;
    int tx = threadIdx.x, ty = threadIdx.y;
#pragma unroll
    for (int i = 0; i < 4; i++)
        tile[ty + 8 * i][tx] =
            g_qkv[(size_t)(t0 + ty + 8 * i) * QKVW + (NH + NKV) * HD + hkv * HD + d0 + tx];
    __syncthreads();
#pragma unroll
    for (int i = 0; i < 4; i++) {
        float v = tile[tx][ty + 8 * i];
        uint16_t h16, l16;
        split1(v, h16, l16);
        size_t o = (size_t)hkv * HD * T + (size_t)(d0 + ty + 8 * i) * T + t0 + tx;
        ((uint16_t*)g_vth)[o] = h16;
        ((uint16_t*)g_vtl)[o] = l16;
    }
}

// ================= plane GEMM: u64 frag loads + HMMA + L2 CTA swizzle =======
#define PSTRIDE 24                    /* u32 per row: 16 data + 8 pad; 24%32=24 -> u64 cf */
#define TILE_U32 (128 * PSTRIDE)      /* 3072 */
#define STAGE_U32 (4 * TILE_U32)      /* AsH AsL BsH BsL */
#define GEMM_SMEM (2 * STAGE_U32 * 4) /* 98304 B */
#define GEMM_GW 8                     /* column-group width for L2 reuse */

__global__ __launch_bounds__(256, 2) void gemm_planes(
    const __nv_bfloat16* __restrict__ Ah, const __nv_bfloat16* __restrict__ Al,
    const __nv_bfloat16* __restrict__ Bh, const __nv_bfloat16* __restrict__ Bl,
    float* __restrict__ C, int M, int N, int K)
{
    extern __shared__ uint32_t smu[];
    int tid  = threadIdx.x;
    int warp = tid >> 5, lane = tid & 31;
    int gid  = lane >> 2, t4 = lane & 3;
    int wm   = (warp >> 2) * 64;
    int wn   = (warp & 3) * 32;

    // grouped CTA raster (L2 reuse of B slabs)
    int lin   = blockIdx.y * gridDim.x + blockIdx.x;
    int gsz   = GEMM_GW * gridDim.y;
    int grp   = lin / gsz;
    int rem   = lin - grp * gsz;
    int bm    = (rem / GEMM_GW) * 128;
    int bn    = (grp * GEMM_GW + (rem % GEMM_GW)) * 128;

    float acc[4][4][4];
#pragma unroll
    for (int mi = 0; mi < 4; mi++)
#pragma unroll
        for (int ni = 0; ni < 4; ni++)
#pragma unroll
            for (int r = 0; r < 4; r++) acc[mi][ni][r] = 0.f;

    uint32_t smbase = (uint32_t)__cvta_generic_to_shared(smu);
    int lr = tid >> 2;     // 0..63
    int lc = tid & 3;      // 16B chunk within 64B row

    auto load_stage = [&](int s, int kt) {
        uint32_t base = smbase + s * STAGE_U32 * 4;
#pragma unroll
        for (int half = 0; half < 2; half++) {
            int r = lr + 64 * half;
            uint32_t d = base + (r * PSTRIDE + lc * 4) * 4;
            cp_async16(d,                    Ah + (size_t)(bm + r) * K + kt + lc * 8);
            cp_async16(d + TILE_U32 * 4,     Al + (size_t)(bm + r) * K + kt + lc * 8);
            cp_async16(d + 2 * TILE_U32 * 4, Bh + (size_t)(bn + r) * K + kt + lc * 8);
            cp_async16(d + 3 * TILE_U32 * 4, Bl + (size_t)(bn + r) * K + kt + lc * 8);
        }
        asm volatile("cp.async.commit_group;\n");
    };

    load_stage(0, 0);
    int niter = K >> 5;

    for (int it = 0; it < niter; it++) {
        int s = it & 1;
        if (it + 1 < niter) {
            load_stage(s ^ 1, (it + 1) << 5);
            asm volatile("cp.async.wait_group 1;\n");
        } else {
            asm volatile("cp.async.wait_group 0;\n");
        }
        __syncthreads();

        const uint32_t* AsH = smu + s * STAGE_U32;
        const uint32_t* AsL = AsH + TILE_U32;
        const uint32_t* BsH = AsH + 2 * TILE_U32;
        const uint32_t* BsL = AsH + 3 * TILE_U32;

#pragma unroll
        for (int kp0 = 0; kp0 < 16; kp0 += 8) {
            uint2 bhf[4], blf[4];
#pragma unroll
            for (int ni = 0; ni < 4; ni++) {
                int n = wn + ni * 8 + gid;
                bhf[ni] = *(const uint2*)&BsH[n * PSTRIDE + kp0 + 2 * t4];
                blf[ni] = *(const uint2*)&BsL[n * PSTRIDE + kp0 + 2 * t4];
            }
#pragma unroll
            for (int mi = 0; mi < 4; mi++) {
                int m = wm + mi * 16 + gid;
                uint2 aA = *(const uint2*)&AsH[m * PSTRIDE + kp0 + 2 * t4];
                uint2 aB = *(const uint2*)&AsH[(m + 8) * PSTRIDE + kp0 + 2 * t4];
                uint2 eA = *(const uint2*)&AsL[m * PSTRIDE + kp0 + 2 * t4];
                uint2 eB = *(const uint2*)&AsL[(m + 8) * PSTRIDE + kp0 + 2 * t4];
#pragma unroll
                for (int ni = 0; ni < 4; ni++) {
                    mma_bf16(acc[mi][ni], aA.x, aB.x, aA.y, aB.y, bhf[ni].x, bhf[ni].y);
                    mma_bf16(acc[mi][ni], aA.x, aB.x, aA.y, aB.y, blf[ni].x, blf[ni].y);
                    mma_bf16(acc[mi][ni], eA.x, eB.x, eA.y, eB.y, bhf[ni].x, bhf[ni].y);
                }
            }
        }
        __syncthreads();
    }

#pragma unroll
    for (int mi = 0; mi < 4; mi++)
#pragma unroll
        for (int ni = 0; ni < 4; ni++) {
            int row = bm + wm + mi * 16 + gid;
            int col = bn + wn + ni * 8 + t4 * 2;
            *(float2*)&C[(size_t)row * N + col] =
                make_float2(acc[mi][ni][0], acc[mi][ni][1]);
            *(float2*)&C[(size_t)(row + 8) * N + col] =
                make_float2(acc[mi][ni][2], acc[mi][ni][3]);
        }
}

// -------- LayerNorm + interleaved RoPE, warp-per-head (flash planes, natural) -
__global__ __launch_bounds__(128) void norm_rope_kernel(
    const int* __restrict__ positions,
    const float* __restrict__ qw, const float* __restrict__ kw)
{
    int t    = blockIdx.x;
    int w    = threadIdx.x >> 5, lane = threadIdx.x & 31;
    int hh   = blockIdx.y * 4 + w;
    bool is_q = hh < NH;
    int head = is_q ? hh : hh - NH;

    const float* src = &g_qkv[(size_t)t * QKVW + (is_q ? head * HD : NH * HD + head * HD)];
    float4 x = *(const float4*)&src[lane * 4];

    float s = x.x + x.y + x.z + x.w;
#pragma unroll
    for (int o = 16; o; o >>= 1) s += __shfl_xor_sync(0xffffffffu, s, o);
    float mean = s * (1.0f / HD);

    float d0 = x.x - mean, d1 = x.y - mean, d2 = x.z - mean, d3 = x.w - mean;
    float s2 = d0 * d0 + d1 * d1 + d2 * d2 + d3 * d3;
#pragma unroll
    for (int o = 16; o; o >>= 1) s2 += __shfl_xor_sync(0xffffffffu, s2, o);
    float rstd = rsqrtf(s2 * (1.0f / HD) + 1e-5f);

    const float* wp = is_q ? &qw[head * HD] : &kw[head * HD];
    float4 wv = *(const float4*)&wp[lane * 4];
    float y[4] = { d0 * rstd * wv.x, d1 * rstd * wv.y,
                   d2 * rstd * wv.z, d3 * rstd * wv.w };

    float fpos = (float)positions[t];
#pragma unroll
    for (int j = 0; j < 2; j++) {
        int p = lane * 2 + j;
        float inv_freq = exp2f(-((float)(2 * p) * (1.0f / HD)) * 13.287712379549449f);
        float f = fpos * inv_freq;
        float sn, cs;
        sincosf(f, &sn, &cs);
        float x1 = y[2 * j], x2 = y[2 * j + 1];
        float o1 = x1 * cs - x2 * sn;
        float o2 = x2 * cs + x1 * sn;
        uint32_t hh32, ll32;
        if (is_q) {
            split2(o1 * SCALE, o2 * SCALE, hh32, ll32);
            ((uint32_t*)g_qh)[(size_t)t * 2048 + head * 64 + p] = hh32;
            ((uint32_t*)g_ql)[(size_t)t * 2048 + head * 64 + p] = ll32;
        } else {
            split2(o1, o2, hh32, ll32);
            ((uint32_t*)g_kh)[(size_t)t * 512 + head * 64 + p] = hh32;
            ((uint32_t*)g_kl)[(size_t)t * 512 + head * 64 + p] = ll32;
        }
    }
}

// ================= flash attention: reg-P + cp.async double-buffered K/V =====
#define QP 68
#define VP 36
#define FQL_O   (128 * QP)
#define FK_O    (2 * 128 * QP)
#define FKBUF   (2 * 64 * QP)
#define FKL_O   (64 * QP)
#define FV_O    (FK_O + 2 * FKBUF)
#define FVBUF   (2 * 128 * VP)
#define FVL_O   (128 * VP)
#define FLASH_U32 (FV_O + 2 * FVBUF)
#define FLASH_SMEM (FLASH_U32 * 4)    /* 212992 B */

__global__ __launch_bounds__(256) void flash_mma_kernel()
{
    extern __shared__ uint32_t smu[];

    int qb  = (gridDim.x - 1) - blockIdx.x;   // heavy blocks first
    int h   = blockIdx.y;
    int hkv = h >> 2;
    int tid = threadIdx.x;
    int w   = tid >> 5, lane = tid & 31;
    int gid = lane >> 2, t4 = lane & 3;
    int r0  = w * 16;

    uint32_t smbase = (uint32_t)__cvta_generic_to_shared(smu);

    const uint4* kh4 = (const uint4*)g_kh + ((size_t)hkv * HD) / 8;
    const uint4* kl4 = (const uint4*)g_kl + ((size_t)hkv * HD) / 8;
    const uint4* vh4 = (const uint4*)g_vth + ((size_t)hkv * HD * T) / 8;
    const uint4* vl4 = (const uint4*)g_vtl + ((size_t)hkv * HD * T) / 8;

    auto load_kv = [&](int kb2) {
        int b = kb2 & 1;
        uint32_t kdst = smbase + (FK_O + b * FKBUF) * 4;
        const uint4* kh = kh4 + (size_t)(kb2 * 64) * 128;
        const uint4* kl = kl4 + (size_t)(kb2 * 64) * 128;
#pragma unroll
        for (int j = 0; j < 4; j++) {
            int idx = tid + 256 * j;
            int r = idx >> 4, u = idx & 15;
            uint32_t d = kdst + (uint32_t)(r * QP + u * 4) * 4;
            cp_async16(d,             kh + r * 128 + u);
            cp_async16(d + FKL_O * 4, kl + r * 128 + u);
        }
        uint32_t vdst = smbase + (FV_O + b * FVBUF) * 4;
        const uint4* vh = vh4 + (size_t)(kb2 * 64) / 8;
        const uint4* vl = vl4 + (size_t)(kb2 * 64) / 8;
#pragma unroll
        for (int j = 0; j < 4; j++) {
            int idx = tid + 256 * j;
            int dd = idx >> 3, u = idx & 7;
            uint32_t d = vdst + (uint32_t)(dd * VP + u * 4) * 4;
            cp_async16(d,             vh + dd * 256 + u);
            cp_async16(d + FVL_O * 4, vl + dd * 256 + u);
        }
        asm volatile("cp.async.commit_group;\n");
    };

    {
        const uint4* qh4 = (const uint4*)g_qh + ((size_t)(qb * 128) * (NH * HD) + h * HD) / 8;
        const uint4* ql4 = (const uint4*)g_ql + ((size_t)(qb * 128) * (NH * HD) + h * HD) / 8;
        for (int idx = tid; idx < 128 * 16; idx += 256) {
            int r = idx >> 4, u = idx & 15;
            *(uint4*)&smu[r * QP + u * 4]         = qh4[r * 512 + u];
            *(uint4*)&smu[FQL_O + r * QP + u * 4] = ql4[r * 512 + u];
        }
    }

    load_kv(0);

    float of[16][4];
#pragma unroll
    for (int ni = 0; ni < 16; ni++)
#pragma unroll
        for (int r = 0; r < 4; r++) of[ni][r] = 0.f;
    float mst0 = -1e30f, mst1 = -1e30f, lst0 = 0.f, lst1 = 0.f;

    int nkb = 2 * qb + 2;
    for (int kb = 0; kb < nkb; kb++) {
        __syncthreads();
        if (kb + 1 < nkb) {
            load_kv(kb + 1);
            asm volatile("cp.async.wait_group 1;\n" ::: "memory");
        } else {
            asm volatile("cp.async.wait_group 0;\n" ::: "memory");
        }
        __syncthreads();

        int b = kb & 1;
        const uint32_t* KHp = smu + FK_O + b * FKBUF;
        const uint32_t* KLp = KHp + FKL_O;
        const uint32_t* VHp = smu + FV_O + b * FVBUF;
        const uint32_t* VLp = VHp + FVL_O;

        float sf[8][4];
#pragma unroll
        for (int ni = 0; ni < 8; ni++)
#pragma unroll
            for (int r = 0; r < 4; r++) sf[ni][r] = 0.f;

#pragma unroll
        for (int ks = 0; ks < 8; ks++) {
            int kp = ks * 8;
            uint32_t a0 = smu[(r0 + gid) * QP + kp + t4];
            uint32_t a1 = smu[(r0 + gid + 8) * QP + kp + t4];
            uint32_t a2 = smu[(r0 + gid) * QP + kp + 4 + t4];
            uint32_t a3 = smu[(r0 + gid + 8) * QP + kp + 4 + t4];
            uint32_t e0 = smu[FQL_O + (r0 + gid) * QP + kp + t4];
            uint32_t e1 = smu[FQL_O + (r0 + gid + 8) * QP + kp + t4];
            uint32_t e2 = smu[FQL_O + (r0 + gid) * QP + kp + 4 + t4];
            uint32_t e3 = smu[FQL_O + (r0 + gid + 8) * QP + kp + 4 + t4];
#pragma unroll
            for (int ni = 0; ni < 8; ni++) {
                int n = ni * 8 + gid;
                uint32_t b0 = KHp[n * QP + kp + t4];
                uint32_t b1 = KHp[n * QP + kp + 4 + t4];
                uint32_t f0 = KLp[n * QP + kp + t4];
                uint32_t f1 = KLp[n * QP + kp + 4 + t4];
                mma_bf16(sf[ni], a0, a1, a2, a3, b0, b1);
                mma_bf16(sf[ni], a0, a1, a2, a3, f0, f1);
                mma_bf16(sf[ni], e0, e1, e2, e3, b0, b1);
            }
        }

        if (kb >= 2 * qb) {
            int R0 = qb * 128 + r0 + gid;
            int R1 = R0 + 8;
            int jb = kb * 64;
#pragma unroll
            for (int ni = 0; ni < 8; ni++) {
                int c0 = jb + ni * 8 + t4 * 2;
                if (c0     > R0) sf[ni][0] = -1e30f;
                if (c0 + 1 > R0) sf[ni][1] = -1e30f;
                if (c0     > R1) sf[ni][2] = -1e30f;
                if (c0 + 1 > R1) sf[ni][3] = -1e30f;
            }
        }

        float mx0 = -1e30f, mx1 = -1e30f;
#pragma unroll
        for (int ni = 0; ni < 8; ni++) {
            mx0 = fmaxf(mx0, fmaxf(sf[ni][0], sf[ni][1]));
            mx1 = fmaxf(mx1, fmaxf(sf[ni][2], sf[ni][3]));
        }
        mx0 = fmaxf(mx0, __shfl_xor_sync(0xffffffffu, mx0, 1));
        mx0 = fmaxf(mx0, __shfl_xor_sync(0xffffffffu, mx0, 2));
        mx1 = fmaxf(mx1, __shfl_xor_sync(0xffffffffu, mx1, 1));
        mx1 = fmaxf(mx1, __shfl_xor_sync(0xffffffffu, mx1, 2));

        float mn0 = fmaxf(mst0, mx0), mn1 = fmaxf(mst1, mx1);
        float a0s = __expf(mst0 - mn0), a1s = __expf(mst1 - mn1);
        mst0 = mn0; mst1 = mn1;

        float ls0 = 0.f, ls1 = 0.f;
#pragma unroll
        for (int ni = 0; ni < 8; ni++) {
            sf[ni][0] = __expf(sf[ni][0] - mn0);
            sf[ni][1] = __expf(sf[ni][1] - mn0);
            sf[ni][2] = __expf(sf[ni][2] - mn1);
            sf[ni][3] = __expf(sf[ni][3] - mn1);
            ls0 += sf[ni][0] + sf[ni][1];
            ls1 += sf[ni][2] + sf[ni][3];
        }
        ls0 += __shfl_xor_sync(0xffffffffu, ls0, 1);
        ls0 += __shfl_xor_sync(0xffffffffu, ls0, 2);
        ls1 += __shfl_xor_sync(0xffffffffu, ls1, 1);
        ls1 += __shfl_xor_sync(0xffffffffu, ls1, 2);
        lst0 = a0s * lst0 + ls0;
        lst1 = a1s * lst1 + ls1;

#pragma unroll
        for (int ni = 0; ni < 16; ni++) {
            of[ni][0] *= a0s; of[ni][1] *= a0s;
            of[ni][2] *= a1s; of[ni][3] *= a1s;
        }

#pragma unroll
        for (int ks = 0; ks < 4; ks++) {
            int kp = ks * 8;
            uint32_t a0, a1, a2, a3, e0, e1, e2, e3;
            split2(sf[2 * ks][0],     sf[2 * ks][1],     a0, e0);
            split2(sf[2 * ks][2],     sf[2 * ks][3],     a1, e1);
            split2(sf[2 * ks + 1][0], sf[2 * ks + 1][1], a2, e2);
            split2(sf[2 * ks + 1][2], sf[2 * ks + 1][3], a3, e3);
#pragma unroll
            for (int ni = 0; ni < 16; ni++) {
                int n = ni * 8 + gid;
                uint32_t b0 = VHp[n * VP + kp + t4];
                uint32_t b1 = VHp[n * VP + kp + 4 + t4];
                uint32_t f0 = VLp[n * VP + kp + t4];
                uint32_t f1 = VLp[n * VP + kp + 4 + t4];
                mma_bf16(of[ni], a0, a1, a2, a3, b0, b1);
                mma_bf16(of[ni], a0, a1, a2, a3, f0, f1);
                mma_bf16(of[ni], e0, e1, e2, e3, b0, b1);
            }
        }
    }

    // ---- epilogue: write A planes (k-permuted for gemm2's u64 frag loads) ----
    float li0 = 1.0f / lst0, li1 = 1.0f / lst1;
    int R0 = qb * 128 + r0 + gid;
    int R1 = R0 + 8;
    uint32_t* pah = (uint32_t*)g_ah;
    uint32_t* pal = (uint32_t*)g_al;
#pragma unroll
    for (int ni = 0; ni < 16; ni++) {
        int q = ni * 4 + t4;
        int colp = h * 64 + ((q & ~7) | perm_pair(q & 7));
        uint32_t hh32, ll32;
        split2(of[ni][0] * li0, of[ni][1] * li0, hh32, ll32);
        pah[(size_t)R0 * 2048 + colp] = hh32;
        pal[(size_t)R0 * 2048 + colp] = ll32;
        split2(of[ni][2] * li1, of[ni][3] * li1, hh32, ll32);
        pah[(size_t)R1 * 2048 + colp] = hh32;
        pal[(size_t)R1 * 2048 + colp] = ll32;
    }
}

// ---------------- launch ----------------
extern "C" void kernel_launch(void* const* d_in, const int* in_sizes, int n_in,
                              void* d_out, int out_size)
{
    const int*   positions = (const int*)d_in[0];
    const float* hidden    = (const float*)d_in[1];
    const float* w_qkv     = (const float*)d_in[2];
    const float* w_o       = (const float*)d_in[3];
    const float* qw        = (const float*)d_in[4];
    const float* kw        = (const float*)d_in[5];
    float*       out       = (float*)d_out;

    float* qkvp;
    __nv_bfloat16 *ahp, *alp, *bhp, *blp;
    cudaGetSymbolAddress((void**)&qkvp, g_qkv);
    cudaGetSymbolAddress((void**)&ahp, g_ah);
    cudaGetSymbolAddress((void**)&alp, g_al);
    cudaGetSymbolAddress((void**)&bhp, g_bh);
    cudaGetSymbolAddress((void**)&blp, g_bl);

    cudaFuncSetAttribute(gemm_planes,
                         cudaFuncAttributeMaxDynamicSharedMemorySize, GEMM_SMEM);
    cudaFuncSetAttribute(flash_mma_kernel,
                         cudaFuncAttributeMaxDynamicSharedMemorySize, FLASH_SMEM);

    // 1) split hidden -> A planes; split+transpose w_qkv -> B planes (permuted)
    split_plane<<<4096, 256>>>((const float2*)hidden,
                               (uint32_t*)ahp, (uint32_t*)alp, T * H / 2);
    split_transpose<<<dim3(QKVW / 32, H / 32), dim3(32, 8)>>>(w_qkv, bhp, blp, H, QKVW);

    // 2) QKV projection (u64-frag bf16x3 HMMA, L2-swizzled raster)
    gemm_planes<<<dim3(QKVW / 128, T / 128), 256, GEMM_SMEM>>>(
        ahp, alp, bhp, blp, qkvp, T, QKVW, H);

    // 3) LayerNorm + RoPE (warp-per-head) -> flash planes; V -> transposed planes
    norm_rope_kernel<<<dim3(T, (NH + NKV) / 4), 128>>>(positions, qw, kw);
    split_transpose_v<<<dim3(T / 32, HD / 32, NKV), dim3(32, 8)>>>();

    // 4) flash attention -> writes permuted A planes directly
    flash_mma_kernel<<<dim3(T / 128, NH), 256, FLASH_SMEM>>>();

    // 5) split+transpose w_o -> B planes (permuted); output projection
    split_transpose<<<dim3(H / 32, (NH * HD) / 32), dim3(32, 8)>>>(w_o, bhp, blp, NH * HD, H);
    gemm_planes<<<dim3(H / 128, T / 128), 256, GEMM_SMEM>>>(
        ahp, alp, bhp, blp, out, T, H, NH * HD);
}

// round 17
// speedup vs baseline: 1.2542x; 1.0476x over previous
#include <cuda_runtime.h>
#include <cuda_bf16.h>
#include <math.h>
#include <stdint.h>

#define T 2048
#define H 4096
#define NH 32
#define NKV 8
#define HD 128
#define QKVW ((NH + 2 * NKV) * HD)   /* 6144 */
#define SCALE 0.08838834764831845f   /* HD^-0.5 */

// ---------------- scratch (static device memory; no allocs allowed) ----------
__device__ float g_qkv[T * QKVW];                                  // fp32 QKV
__device__ __align__(256) __nv_bfloat16 g_ah[T * H],      g_al[T * H];        // A planes (k-permuted)
__device__ __align__(256) __nv_bfloat16 g_bh[H * QKVW],   g_bl[H * QKVW];     // B planes ([N][K], k-permuted)
__device__ __align__(256) __nv_bfloat16 g_qh[T * NH * HD], g_ql[T * NH * HD]; // flash planes (k-permuted)
__device__ __align__(256) __nv_bfloat16 g_kh[T * NKV * HD], g_kl[T * NKV * HD];
__device__ __align__(256) __nv_bfloat16 g_vth[NKV * HD * T], g_vtl[NKV * HD * T]; // V^T [hkv][d][t] (t-permuted)

// ================= helpers ================
__device__ __forceinline__ void mma_bf16(float c[4],
    uint32_t a0, uint32_t a1, uint32_t a2, uint32_t a3,
    uint32_t b0, uint32_t b1)
{
    asm volatile(
        "mma.sync.aligned.m16n8k16.row.col.f32.bf16.bf16.f32 "
        "{%0,%1,%2,%3},{%4,%5,%6,%7},{%8,%9},{%0,%1,%2,%3};\n"
        : "+f"(c[0]), "+f"(c[1]), "+f"(c[2]), "+f"(c[3])
        : "r"(a0), "r"(a1), "r"(a2), "r"(a3), "r"(b0), "r"(b1));
}

__device__ __forceinline__ uint32_t pack_hi16(float x0, float x1)
{
    uint32_t r;
    asm("prmt.b32 %0, %1, %2, 0x7632;"
        : "=r"(r) : "r"(__float_as_uint(x0)), "r"(__float_as_uint(x1)));
    return r;
}

__device__ __forceinline__ void split2(float x0, float x1, uint32_t& h, uint32_t& l)
{
    h = pack_hi16(x0, x1);
    float l0 = x0 - __uint_as_float(__float_as_uint(x0) & 0xffff0000u);
    float l1 = x1 - __uint_as_float(__float_as_uint(x1) & 0xffff0000u);
    l = pack_hi16(l0, l1);
}

__device__ __forceinline__ void split1(float v, uint16_t& h16, uint16_t& l16)
{
    uint32_t u = __float_as_uint(v);
    h16 = (uint16_t)(u >> 16);
    float lo = v - __uint_as_float(u & 0xffff0000u);
    l16 = (uint16_t)(__float_as_uint(lo) >> 16);
}

__device__ __forceinline__ void cp_async16(uint32_t dst, const void* src)
{
    asm volatile("cp.async.cg.shared.global [%0], [%1], 16;\n"
                 :: "r"(dst), "l"(src));
}

// k-pair permutation within each k16 group (8 bf16 pairs):
// slot(p) = ((p&3)<<1)|(p>>2) -> frag pairs (t4, t4+4) become adjacent u64.
__device__ __forceinline__ int perm_pair(int p) { return ((p & 3) << 1) | (p >> 2); }
__device__ __forceinline__ int perm_elem(int k)
{
    int p = (k >> 1) & 7;
    return (k & ~15) | (perm_pair(p) << 1) | (k & 1);
}

// ================= prep kernels ================
__global__ void split_plane(const float2* __restrict__ in,
    uint32_t* __restrict__ hi, uint32_t* __restrict__ lo, int npairs)
{
    for (int i = blockIdx.x * blockDim.x + threadIdx.x; i < npairs;
         i += gridDim.x * blockDim.x) {
        float2 v = in[i];
        uint32_t h, l;
        split2(v.x, v.y, h, l);
        int o = (i & ~7) | perm_pair(i & 7);
        hi[o] = h; lo[o] = l;
    }
}

__global__ void split_transpose(const float* __restrict__ B,
    __nv_bfloat16* __restrict__ Bth, __nv_bfloat16* __restrict__ Btl,
    int K, int N)
{
    __shared__ float tile[32][33];
    int n0 = blockIdx.x * 32, k0 = blockIdx.y * 32;
    int tx = threadIdx.x, ty = threadIdx.y;
#pragma unroll
    for (int i = 0; i < 4; i++)
        tile[ty + 8 * i][tx] = B[(size_t)(k0 + ty + 8 * i) * N + n0 + tx];
    __syncthreads();
    int kp = perm_elem(k0 + tx);
#pragma unroll
    for (int i = 0; i < 4; i++) {
        float v = tile[tx][ty + 8 * i];
        uint16_t h16, l16;
        split1(v, h16, l16);
        size_t o = (size_t)(n0 + ty + 8 * i) * K + kp;
        ((uint16_t*)Bth)[o] = h16;
        ((uint16_t*)Btl)[o] = l16;
    }
}

// V region of g_qkv -> V^T planes [hkv][d][t], t-permuted for u64 frag loads
__global__ void split_transpose_v()
{
    __shared__ float tile[32][33];
    int t0 = blockIdx.x * 32, d0 = blockIdx.y * 32, hkv = blockIdx.z;
    int tx = threadIdx.x, ty = threadIdx.y;
#pragma unroll
    for (int i = 0; i < 4; i++)
        tile[ty + 8 * i][tx] =
            g_qkv[(size_t)(t0 + ty + 8 * i) * QKVW + (NH + NKV) * HD + hkv * HD + d0 + tx];
    __syncthreads();
    int tp = perm_elem(t0 + tx);
#pragma unroll
    for (int i = 0; i < 4; i++) {
        float v = tile[tx][ty + 8 * i];
        uint16_t h16, l16;
        split1(v, h16, l16);
        size_t o = (size_t)hkv * HD * T + (size_t)(d0 + ty + 8 * i) * T + tp;
        ((uint16_t*)g_vth)[o] = h16;
        ((uint16_t*)g_vtl)[o] = l16;
    }
}

// ================= plane GEMM: u64 frag loads + HMMA + L2 CTA swizzle =======
#define PSTRIDE 24                    /* u32 per row: 16 data + 8 pad; u64 cf */
#define TILE_U32 (128 * PSTRIDE)      /* 3072 */
#define STAGE_U32 (4 * TILE_U32)      /* AsH AsL BsH BsL */
#define GEMM_SMEM (2 * STAGE_U32 * 4) /* 98304 B */
#define GEMM_GW 8                     /* column-group width for L2 reuse */

__global__ __launch_bounds__(256, 2) void gemm_planes(
    const __nv_bfloat16* __restrict__ Ah, const __nv_bfloat16* __restrict__ Al,
    const __nv_bfloat16* __restrict__ Bh, const __nv_bfloat16* __restrict__ Bl,
    float* __restrict__ C, int M, int N, int K)
{
    extern __shared__ uint32_t smu[];
    int tid  = threadIdx.x;
    int warp = tid >> 5, lane = tid & 31;
    int gid  = lane >> 2, t4 = lane & 3;
    int wm   = (warp >> 2) * 64;
    int wn   = (warp & 3) * 32;

    int lin   = blockIdx.y * gridDim.x + blockIdx.x;
    int gsz   = GEMM_GW * gridDim.y;
    int grp   = lin / gsz;
    int rem   = lin - grp * gsz;
    int bm    = (rem / GEMM_GW) * 128;
    int bn    = (grp * GEMM_GW + (rem % GEMM_GW)) * 128;

    float acc[4][4][4];
#pragma unroll
    for (int mi = 0; mi < 4; mi++)
#pragma unroll
        for (int ni = 0; ni < 4; ni++)
#pragma unroll
            for (int r = 0; r < 4; r++) acc[mi][ni][r] = 0.f;

    uint32_t smbase = (uint32_t)__cvta_generic_to_shared(smu);
    int lr = tid >> 2;
    int lc = tid & 3;

    auto load_stage = [&](int s, int kt) {
        uint32_t base = smbase + s * STAGE_U32 * 4;
#pragma unroll
        for (int half = 0; half < 2; half++) {
            int r = lr + 64 * half;
            uint32_t d = base + (r * PSTRIDE + lc * 4) * 4;
            cp_async16(d,                    Ah + (size_t)(bm + r) * K + kt + lc * 8);
            cp_async16(d + TILE_U32 * 4,     Al + (size_t)(bm + r) * K + kt + lc * 8);
            cp_async16(d + 2 * TILE_U32 * 4, Bh + (size_t)(bn + r) * K + kt + lc * 8);
            cp_async16(d + 3 * TILE_U32 * 4, Bl + (size_t)(bn + r) * K + kt + lc * 8);
        }
        asm volatile("cp.async.commit_group;\n");
    };

    load_stage(0, 0);
    int niter = K >> 5;

    for (int it = 0; it < niter; it++) {
        int s = it & 1;
        if (it + 1 < niter) {
            load_stage(s ^ 1, (it + 1) << 5);
            asm volatile("cp.async.wait_group 1;\n");
        } else {
            asm volatile("cp.async.wait_group 0;\n");
        }
        __syncthreads();

        const uint32_t* AsH = smu + s * STAGE_U32;
        const uint32_t* AsL = AsH + TILE_U32;
        const uint32_t* BsH = AsH + 2 * TILE_U32;
        const uint32_t* BsL = AsH + 3 * TILE_U32;

#pragma unroll
        for (int kp0 = 0; kp0 < 16; kp0 += 8) {
            uint2 bhf[4], blf[4];
#pragma unroll
            for (int ni = 0; ni < 4; ni++) {
                int n = wn + ni * 8 + gid;
                bhf[ni] = *(const uint2*)&BsH[n * PSTRIDE + kp0 + 2 * t4];
                blf[ni] = *(const uint2*)&BsL[n * PSTRIDE + kp0 + 2 * t4];
            }
#pragma unroll
            for (int mi = 0; mi < 4; mi++) {
                int m = wm + mi * 16 + gid;
                uint2 aA = *(const uint2*)&AsH[m * PSTRIDE + kp0 + 2 * t4];
                uint2 aB = *(const uint2*)&AsH[(m + 8) * PSTRIDE + kp0 + 2 * t4];
                uint2 eA = *(const uint2*)&AsL[m * PSTRIDE + kp0 + 2 * t4];
                uint2 eB = *(const uint2*)&AsL[(m + 8) * PSTRIDE + kp0 + 2 * t4];
#pragma unroll
                for (int ni = 0; ni < 4; ni++) {
                    mma_bf16(acc[mi][ni], aA.x, aB.x, aA.y, aB.y, bhf[ni].x, bhf[ni].y);
                    mma_bf16(acc[mi][ni], aA.x, aB.x, aA.y, aB.y, blf[ni].x, blf[ni].y);
                    mma_bf16(acc[mi][ni], eA.x, eB.x, eA.y, eB.y, bhf[ni].x, bhf[ni].y);
                }
            }
        }
        __syncthreads();
    }

#pragma unroll
    for (int mi = 0; mi < 4; mi++)
#pragma unroll
        for (int ni = 0; ni < 4; ni++) {
            int row = bm + wm + mi * 16 + gid;
            int col = bn + wn + ni * 8 + t4 * 2;
            *(float2*)&C[(size_t)row * N + col] =
                make_float2(acc[mi][ni][0], acc[mi][ni][1]);
            *(float2*)&C[(size_t)(row + 8) * N + col] =
                make_float2(acc[mi][ni][2], acc[mi][ni][3]);
        }
}

// -------- LayerNorm + interleaved RoPE, warp-per-head (permuted flash planes) -
__global__ __launch_bounds__(128) void norm_rope_kernel(
    const int* __restrict__ positions,
    const float* __restrict__ qw, const float* __restrict__ kw)
{
    int t    = blockIdx.x;
    int w    = threadIdx.x >> 5, lane = threadIdx.x & 31;
    int hh   = blockIdx.y * 4 + w;
    bool is_q = hh < NH;
    int head = is_q ? hh : hh - NH;

    const float* src = &g_qkv[(size_t)t * QKVW + (is_q ? head * HD : NH * HD + head * HD)];
    float4 x = *(const float4*)&src[lane * 4];

    float s = x.x + x.y + x.z + x.w;
#pragma unroll
    for (int o = 16; o; o >>= 1) s += __shfl_xor_sync(0xffffffffu, s, o);
    float mean = s * (1.0f / HD);

    float d0 = x.x - mean, d1 = x.y - mean, d2 = x.z - mean, d3 = x.w - mean;
    float s2 = d0 * d0 + d1 * d1 + d2 * d2 + d3 * d3;
#pragma unroll
    for (int o = 16; o; o >>= 1) s2 += __shfl_xor_sync(0xffffffffu, s2, o);
    float rstd = rsqrtf(s2 * (1.0f / HD) + 1e-5f);

    const float* wp = is_q ? &qw[head * HD] : &kw[head * HD];
    float4 wv = *(const float4*)&wp[lane * 4];
    float y[4] = { d0 * rstd * wv.x, d1 * rstd * wv.y,
                   d2 * rstd * wv.z, d3 * rstd * wv.w };

    float fpos = (float)positions[t];
#pragma unroll
    for (int j = 0; j < 2; j++) {
        int p = lane * 2 + j;
        float inv_freq = exp2f(-((float)(2 * p) * (1.0f / HD)) * 13.287712379549449f);
        float f = fpos * inv_freq;
        float sn, cs;
        sincosf(f, &sn, &cs);
        float x1 = y[2 * j], x2 = y[2 * j + 1];
        float o1 = x1 * cs - x2 * sn;
        float o2 = x2 * cs + x1 * sn;
        int pp = (p & ~7) | perm_pair(p & 7);     // k-pair permuted slot
        uint32_t hh32, ll32;
        if (is_q) {
            split2(o1 * SCALE, o2 * SCALE, hh32, ll32);
            ((uint32_t*)g_qh)[(size_t)t * 2048 + head * 64 + pp] = hh32;
            ((uint32_t*)g_ql)[(size_t)t * 2048 + head * 64 + pp] = ll32;
        } else {
            split2(o1, o2, hh32, ll32);
            ((uint32_t*)g_kh)[(size_t)t * 512 + head * 64 + pp] = hh32;
            ((uint32_t*)g_kl)[(size_t)t * 512 + head * 64 + pp] = ll32;
        }
    }
}

// ================= flash attention: u64 frags + reg-P + double-buffered K/V ==
#define QP 72   /* u32 per row: 64 data + 8 pad; u64 loads: 36g+t4 mod 16 cf */
#define VP 40   /* u32 per row: 32 data + 8 pad; u64 loads: 20g+t4 mod 16 cf */
#define FQL_O   (128 * QP)            /* 9216  */
#define FK_O    (2 * 128 * QP)        /* 18432 */
#define FKBUF   (2 * 64 * QP)         /* 9216  */
#define FKL_O   (64 * QP)             /* 4608  */
#define FV_O    (FK_O + 2 * FKBUF)    /* 36864 */
#define FVBUF   (2 * 128 * VP)        /* 10240 */
#define FVL_O   (128 * VP)            /* 5120  */
#define FLASH_U32 (FV_O + 2 * FVBUF)  /* 57344 */
#define FLASH_SMEM (FLASH_U32 * 4)    /* 229376 B */

__global__ __launch_bounds__(256) void flash_mma_kernel()
{
    extern __shared__ uint32_t smu[];

    int qb  = (gridDim.x - 1) - blockIdx.x;   // heavy blocks first
    int h   = blockIdx.y;
    int hkv = h >> 2;
    int tid = threadIdx.x;
    int w   = tid >> 5, lane = tid & 31;
    int gid = lane >> 2, t4 = lane & 3;
    int r0  = w * 16;

    uint32_t smbase = (uint32_t)__cvta_generic_to_shared(smu);

    const uint4* kh4 = (const uint4*)g_kh + ((size_t)hkv * HD) / 8;
    const uint4* kl4 = (const uint4*)g_kl + ((size_t)hkv * HD) / 8;
    const uint4* vh4 = (const uint4*)g_vth + ((size_t)hkv * HD * T) / 8;
    const uint4* vl4 = (const uint4*)g_vtl + ((size_t)hkv * HD * T) / 8;

    auto load_kv = [&](int kb2) {
        int b = kb2 & 1;
        uint32_t kdst = smbase + (FK_O + b * FKBUF) * 4;
        const uint4* kh = kh4 + (size_t)(kb2 * 64) * 128;
        const uint4* kl = kl4 + (size_t)(kb2 * 64) * 128;
#pragma unroll
        for (int j = 0; j < 4; j++) {
            int idx = tid + 256 * j;
            int r = idx >> 4, u = idx & 15;
            uint32_t d = kdst + (uint32_t)(r * QP + u * 4) * 4;
            cp_async16(d,             kh + r * 128 + u);
            cp_async16(d + FKL_O * 4, kl + r * 128 + u);
        }
        uint32_t vdst = smbase + (FV_O + b * FVBUF) * 4;
        const uint4* vh = vh4 + (size_t)(kb2 * 64) / 8;
        const uint4* vl = vl4 + (size_t)(kb2 * 64) / 8;
#pragma unroll
        for (int j = 0; j < 4; j++) {
            int idx = tid + 256 * j;
            int dd = idx >> 3, u = idx & 7;
            uint32_t d = vdst + (uint32_t)(dd * VP + u * 4) * 4;
            cp_async16(d,             vh + dd * 256 + u);
            cp_async16(d + FVL_O * 4, vl + dd * 256 + u);
        }
        asm volatile("cp.async.commit_group;\n");
    };

    {
        const uint4* qh4 = (const uint4*)g_qh + ((size_t)(qb * 128) * (NH * HD) + h * HD) / 8;
        const uint4* ql4 = (const uint4*)g_ql + ((size_t)(qb * 128) * (NH * HD) + h * HD) / 8;
        for (int idx = tid; idx < 128 * 16; idx += 256) {
            int r = idx >> 4, u = idx & 15;
            *(uint4*)&smu[r * QP + u * 4]         = qh4[r * 512 + u];
            *(uint4*)&smu[FQL_O + r * QP + u * 4] = ql4[r * 512 + u];
        }
    }

    load_kv(0);

    float of[16][4];
#pragma unroll
    for (int ni = 0; ni < 16; ni++)
#pragma unroll
        for (int r = 0; r < 4; r++) of[ni][r] = 0.f;
    float mst0 = -1e30f, mst1 = -1e30f, lst0 = 0.f, lst1 = 0.f;

    int nkb = 2 * qb + 2;
    for (int kb = 0; kb < nkb; kb++) {
        __syncthreads();
        if (kb + 1 < nkb) {
            load_kv(kb + 1);
            asm volatile("cp.async.wait_group 1;\n" ::: "memory");
        } else {
            asm volatile("cp.async.wait_group 0;\n" ::: "memory");
        }
        __syncthreads();

        int b = kb & 1;
        const uint32_t* KHp = smu + FK_O + b * FKBUF;
        const uint32_t* KLp = KHp + FKL_O;
        const uint32_t* VHp = smu + FV_O + b * FVBUF;
        const uint32_t* VLp = VHp + FVL_O;

        // ---- S = Q @ K^T : u64 frag loads ----
        float sf[8][4];
#pragma unroll
        for (int ni = 0; ni < 8; ni++)
#pragma unroll
            for (int r = 0; r < 4; r++) sf[ni][r] = 0.f;

#pragma unroll
        for (int ks = 0; ks < 8; ks++) {
            int kp = ks * 8;
            uint2 A0 = *(const uint2*)&smu[(r0 + gid) * QP + kp + 2 * t4];
            uint2 A1 = *(const uint2*)&smu[(r0 + gid + 8) * QP + kp + 2 * t4];
            uint2 E0 = *(const uint2*)&smu[FQL_O + (r0 + gid) * QP + kp + 2 * t4];
            uint2 E1 = *(const uint2*)&smu[FQL_O + (r0 + gid + 8) * QP + kp + 2 * t4];
#pragma unroll
            for (int ni = 0; ni < 8; ni++) {
                int n = ni * 8 + gid;
                uint2 B = *(const uint2*)&KHp[n * QP + kp + 2 * t4];
                uint2 F = *(const uint2*)&KLp[n * QP + kp + 2 * t4];
                mma_bf16(sf[ni], A0.x, A1.x, A0.y, A1.y, B.x, B.y);
                mma_bf16(sf[ni], A0.x, A1.x, A0.y, A1.y, F.x, F.y);
                mma_bf16(sf[ni], E0.x, E1.x, E0.y, E1.y, B.x, B.y);
            }
        }

        if (kb >= 2 * qb) {
            int R0 = qb * 128 + r0 + gid;
            int R1 = R0 + 8;
            int jb = kb * 64;
#pragma unroll
            for (int ni = 0; ni < 8; ni++) {
                int c0 = jb + ni * 8 + t4 * 2;
                if (c0     > R0) sf[ni][0] = -1e30f;
                if (c0 + 1 > R0) sf[ni][1] = -1e30f;
                if (c0     > R1) sf[ni][2] = -1e30f;
                if (c0 + 1 > R1) sf[ni][3] = -1e30f;
            }
        }

        float mx0 = -1e30f, mx1 = -1e30f;
#pragma unroll
        for (int ni = 0; ni < 8; ni++) {
            mx0 = fmaxf(mx0, fmaxf(sf[ni][0], sf[ni][1]));
            mx1 = fmaxf(mx1, fmaxf(sf[ni][2], sf[ni][3]));
        }
        mx0 = fmaxf(mx0, __shfl_xor_sync(0xffffffffu, mx0, 1));
        mx0 = fmaxf(mx0, __shfl_xor_sync(0xffffffffu, mx0, 2));
        mx1 = fmaxf(mx1, __shfl_xor_sync(0xffffffffu, mx1, 1));
        mx1 = fmaxf(mx1, __shfl_xor_sync(0xffffffffu, mx1, 2));

        float mn0 = fmaxf(mst0, mx0), mn1 = fmaxf(mst1, mx1);
        float a0s = __expf(mst0 - mn0), a1s = __expf(mst1 - mn1);
        mst0 = mn0; mst1 = mn1;

        float ls0 = 0.f, ls1 = 0.f;
#pragma unroll
        for (int ni = 0; ni < 8; ni++) {
            sf[ni][0] = __expf(sf[ni][0] - mn0);
            sf[ni][1] = __expf(sf[ni][1] - mn0);
            sf[ni][2] = __expf(sf[ni][2] - mn1);
            sf[ni][3] = __expf(sf[ni][3] - mn1);
            ls0 += sf[ni][0] + sf[ni][1];
            ls1 += sf[ni][2] + sf[ni][3];
        }
        ls0 += __shfl_xor_sync(0xffffffffu, ls0, 1);
        ls0 += __shfl_xor_sync(0xffffffffu, ls0, 2);
        ls1 += __shfl_xor_sync(0xffffffffu, ls1, 1);
        ls1 += __shfl_xor_sync(0xffffffffu, ls1, 2);
        lst0 = a0s * lst0 + ls0;
        lst1 = a1s * lst1 + ls1;

#pragma unroll
        for (int ni = 0; ni < 16; ni++) {
            of[ni][0] *= a0s; of[ni][1] *= a0s;
            of[ni][2] *= a1s; of[ni][3] *= a1s;
        }

        // ---- O += P @ V : reg-P, u64 V frag loads (V t-permuted) ----
#pragma unroll
        for (int ks = 0; ks < 4; ks++) {
            int kp = ks * 8;
            uint32_t a0, a1, a2, a3, e0, e1, e2, e3;
            split2(sf[2 * ks][0],     sf[2 * ks][1],     a0, e0);
            split2(sf[2 * ks][2],     sf[2 * ks][3],     a1, e1);
            split2(sf[2 * ks + 1][0], sf[2 * ks + 1][1], a2, e2);
            split2(sf[2 * ks + 1][2], sf[2 * ks + 1][3], a3, e3);
#pragma unroll
            for (int ni = 0; ni < 16; ni++) {
                int n = ni * 8 + gid;
                uint2 B = *(const uint2*)&VHp[n * VP + kp + 2 * t4];
                uint2 F = *(const uint2*)&VLp[n * VP + kp + 2 * t4];
                mma_bf16(of[ni], a0, a1, a2, a3, B.x, B.y);
                mma_bf16(of[ni], a0, a1, a2, a3, F.x, F.y);
                mma_bf16(of[ni], e0, e1, e2, e3, B.x, B.y);
            }
        }
    }

    // ---- epilogue: write A planes (k-permuted for gemm2's u64 frag loads) ----
    float li0 = 1.0f / lst0, li1 = 1.0f / lst1;
    int R0 = qb * 128 + r0 + gid;
    int R1 = R0 + 8;
    uint32_t* pah = (uint32_t*)g_ah;
    uint32_t* pal = (uint32_t*)g_al;
#pragma unroll
    for (int ni = 0; ni < 16; ni++) {
        int q = ni * 4 + t4;
        int colp = h * 64 + ((q & ~7) | perm_pair(q & 7));
        uint32_t hh32, ll32;
        split2(of[ni][0] * li0, of[ni][1] * li0, hh32, ll32);
        pah[(size_t)R0 * 2048 + colp] = hh32;
        pal[(size_t)R0 * 2048 + colp] = ll32;
        split2(of[ni][2] * li1, of[ni][3] * li1, hh32, ll32);
        pah[(size_t)R1 * 2048 + colp] = hh32;
        pal[(size_t)R1 * 2048 + colp] = ll32;
    }
}

// ---------------- launch ----------------
extern "C" void kernel_launch(void* const* d_in, const int* in_sizes, int n_in,
                              void* d_out, int out_size)
{
    const int*   positions = (const int*)d_in[0];
    const float* hidden    = (const float*)d_in[1];
    const float* w_qkv     = (const float*)d_in[2];
    const float* w_o       = (const float*)d_in[3];
    const float* qw        = (const float*)d_in[4];
    const float* kw        = (const float*)d_in[5];
    float*       out       = (float*)d_out;

    float* qkvp;
    __nv_bfloat16 *ahp, *alp, *bhp, *blp;
    cudaGetSymbolAddress((void**)&qkvp, g_qkv);
    cudaGetSymbolAddress((void**)&ahp, g_ah);
    cudaGetSymbolAddress((void**)&alp, g_al);
    cudaGetSymbolAddress((void**)&bhp, g_bh);
    cudaGetSymbolAddress((void**)&blp, g_bl);

    cudaFuncSetAttribute(gemm_planes,
                         cudaFuncAttributeMaxDynamicSharedMemorySize, GEMM_SMEM);
    cudaFuncSetAttribute(flash_mma_kernel,
                         cudaFuncAttributeMaxDynamicSharedMemorySize, FLASH_SMEM);

    // 1) split hidden -> A planes; split+transpose w_qkv -> B planes (permuted)
    split_plane<<<4096, 256>>>((const float2*)hidden,
                               (uint32_t*)ahp, (uint32_t*)alp, T * H / 2);
    split_transpose<<<dim3(QKVW / 32, H / 32), dim3(32, 8)>>>(w_qkv, bhp, blp, H, QKVW);

    // 2) QKV projection (u64-frag bf16x3 HMMA, L2-swizzled raster)
    gemm_planes<<<dim3(QKVW / 128, T / 128), 256, GEMM_SMEM>>>(
        ahp, alp, bhp, blp, qkvp, T, QKVW, H);

    // 3) LayerNorm + RoPE (warp-per-head) -> permuted flash planes; V -> permuted V^T
    norm_rope_kernel<<<dim3(T, (NH + NKV) / 4), 128>>>(positions, qw, kw);
    split_transpose_v<<<dim3(T / 32, HD / 32, NKV), dim3(32, 8)>>>();

    // 4) flash attention (u64 frags) -> writes permuted A planes directly
    flash_mma_kernel<<<dim3(T / 128, NH), 256, FLASH_SMEM>>>();

    // 5) split+transpose w_o -> B planes (permuted); output projection
    split_transpose<<<dim3(H / 32, (NH * HD) / 32), dim3(32, 8)>>>(w_o, bhp, blp, NH * HD, H);
    gemm_planes<<<dim3(H / 128, T / 128), 256, GEMM_SMEM>>>(
        ahp, alp, bhp, blp, out, T, H, NH * HD);
}